// round 5
// baseline (speedup 1.0000x reference)
#include <cuda_runtime.h>
#include <math.h>

#define DM 1024
#define NH 16
#define DK 64
#define SEQ 2048
#define NTOK 4096   // B * SEQ

// ---------------- scratch (device globals) ----------------
__device__ float g_WQP[DM * DM];
__device__ float g_WKP[DM * DM];
__device__ float g_WVR[DM * DM];
__device__ float g_WOR[DM * DM];
__device__ float g_BQP[DM];
__device__ float g_BKP[DM];
__device__ float g_QR[NTOK * DM];
__device__ float g_KR[NTOK * DM];
__device__ float g_VR[NTOK * DM];
__device__ float g_QF[NTOK * DM];
__device__ float g_KF[NTOK * DM];
__device__ float g_VP[NTOK * DM];
__device__ float g_CTX[NTOK * DM];

// ---------------- helpers ----------------
__device__ __forceinline__ float rna_tf32(float x) {
    unsigned u;
    asm("cvt.rna.tf32.f32 %0, %1;" : "=r"(u) : "f"(x));
    return __uint_as_float(u);
}

__device__ __forceinline__ void mma8(float* c, const unsigned* a, unsigned b0, unsigned b1) {
    asm volatile(
        "mma.sync.aligned.m16n8k8.row.col.f32.tf32.tf32.f32 "
        "{%0,%1,%2,%3},{%4,%5,%6,%7},{%8,%9},{%0,%1,%2,%3};"
        : "+f"(c[0]), "+f"(c[1]), "+f"(c[2]), "+f"(c[3])
        : "r"(a[0]), "r"(a[1]), "r"(a[2]), "r"(a[3]), "r"(b0), "r"(b1));
}

__device__ __forceinline__ void cp16(float* dst_smem, const float* src) {
    unsigned s = (unsigned)__cvta_generic_to_shared(dst_smem);
    asm volatile("cp.async.cg.shared.global [%0], [%1], 16;\n" :: "r"(s), "l"(src));
}
__device__ __forceinline__ void cp_commit() {
    asm volatile("cp.async.commit_group;\n");
}
template <int N>
__device__ __forceinline__ void cp_wait() {
    asm volatile("cp.async.wait_group %0;\n" :: "n"(N));
}

// ---------------- prepass: tf32-round a tensor (grid-stride, high MLP) -------------
__global__ void round_copy(const float* __restrict__ src, float* __restrict__ dst, int n4) {
    int stride = gridDim.x * blockDim.x;
    for (int i = blockIdx.x * blockDim.x + threadIdx.x; i < n4; i += stride) {
        float4 v = *(const float4*)&src[(size_t)i << 2];
        v.x = rna_tf32(v.x); v.y = rna_tf32(v.y);
        v.z = rna_tf32(v.z); v.w = rna_tf32(v.w);
        *(float4*)&dst[(size_t)i << 2] = v;
    }
}

// ---------------- fold per-head feature-map weights into projection ----------------
__global__ void fold_weights(const float* __restrict__ w, const float* __restrict__ b,
                             const float* __restrict__ wn, const float* __restrict__ bn,
                             float* __restrict__ wout, float* __restrict__ bout) {
    int idx = blockIdx.x * blockDim.x + threadIdx.x;
    if (idx >= DM * DM) return;
    int i = idx >> 10;
    int j = idx & 1023;
    int h = j >> 6, jj = j & 63;
    const float* wrow = w + i * DM + h * DK;
    float acc = 0.f;
#pragma unroll 8
    for (int d = 0; d < DK; d++) acc += wrow[d] * wn[d * DK + jj];
    wout[idx] = rna_tf32(acc);
    if (i == 0) {
        float bb = bn[jj];
        for (int d = 0; d < DK; d++) bb += b[h * DK + d] * wn[d * DK + jj];
        bout[j] = bb;
    }
}

// ---------------- tf32 TC GEMM, cp.async double-buffered ----------------
// BM=128 BN=256 BK=32; 256 thr / 8 warps (2x4); warp tile 64x64.
#define GBM 128
#define GBN 256
#define GBK 32
#define GAS 36
#define GBS 264
#define GEMM_SMEM ((2 * GBM * GAS + 2 * GBK * GBS) * 4)

__global__ void __launch_bounds__(256) gemm_tc(
    const float* __restrict__ A, const float* __restrict__ W,
    const float* __restrict__ bias, float* __restrict__ C, int act) {
    extern __shared__ __align__(16) float sg[];
    float* As = sg;                       // [2][128][36]
    float* Bs = sg + 2 * GBM * GAS;       // [2][32][264]

    int tid = threadIdx.x;
    int warp = tid >> 5, lane = tid & 31;
    int g = lane >> 2, tig = lane & 3;
    int wm = warp >> 2, wn = warp & 3;
    int bm = blockIdx.y * GBM, bn = blockIdx.x * GBN;

    // loader coords: A 4 float4, B 8 float4 per thread
    int ar[4], ak[4], bkr[8], bn4[8];
#pragma unroll
    for (int i = 0; i < 4; i++) {
        int idx = tid + 256 * i;
        ar[i] = idx >> 3;  ak[i] = (idx & 7) << 2;
    }
#pragma unroll
    for (int i = 0; i < 8; i++) {
        int idx = tid + 256 * i;
        bkr[i] = idx >> 6;  bn4[i] = (idx & 63) << 2;
    }

    float acc[4][8][4];
#pragma unroll
    for (int m = 0; m < 4; m++)
#pragma unroll
        for (int j = 0; j < 8; j++)
#pragma unroll
            for (int t = 0; t < 4; t++) acc[m][j][t] = 0.f;

    // prologue
#pragma unroll
    for (int i = 0; i < 4; i++)
        cp16(&As[ar[i] * GAS + ak[i]], &A[(size_t)(bm + ar[i]) * DM + ak[i]]);
#pragma unroll
    for (int i = 0; i < 8; i++)
        cp16(&Bs[bkr[i] * GBS + bn4[i]], &W[(size_t)bkr[i] * DM + bn + bn4[i]]);
    cp_commit();

    const int NK = DM / GBK;
    for (int kt = 0; kt < NK; kt++) {
        int buf = kt & 1;
        float* Ab = As + buf * GBM * GAS;
        float* Bb = Bs + buf * GBK * GBS;
        __syncthreads();
        if (kt + 1 < NK) {
            int k0n = (kt + 1) * GBK;
            float* An = As + (buf ^ 1) * GBM * GAS;
            float* Bn = Bs + (buf ^ 1) * GBK * GBS;
#pragma unroll
            for (int i = 0; i < 4; i++)
                cp16(&An[ar[i] * GAS + ak[i]], &A[(size_t)(bm + ar[i]) * DM + k0n + ak[i]]);
#pragma unroll
            for (int i = 0; i < 8; i++)
                cp16(&Bn[bkr[i] * GBS + bn4[i]], &W[(size_t)(k0n + bkr[i]) * DM + bn + bn4[i]]);
            cp_commit();
            cp_wait<1>();
        } else {
            cp_wait<0>();
        }
        __syncthreads();

#pragma unroll
        for (int s = 0; s < 4; s++) {
            unsigned a[4][4], bb[8][2];
#pragma unroll
            for (int m = 0; m < 4; m++) {
                int m0 = wm * 64 + m * 16;
                a[m][0] = __float_as_uint(Ab[(m0 + g) * GAS + 8 * s + tig]);
                a[m][1] = __float_as_uint(Ab[(m0 + g + 8) * GAS + 8 * s + tig]);
                a[m][2] = __float_as_uint(Ab[(m0 + g) * GAS + 8 * s + tig + 4]);
                a[m][3] = __float_as_uint(Ab[(m0 + g + 8) * GAS + 8 * s + tig + 4]);
            }
#pragma unroll
            for (int j = 0; j < 8; j++) {
                int n0 = wn * 64 + j * 8;
                bb[j][0] = __float_as_uint(Bb[(8 * s + tig) * GBS + n0 + g]);
                bb[j][1] = __float_as_uint(Bb[(8 * s + tig + 4) * GBS + n0 + g]);
            }
#pragma unroll
            for (int m = 0; m < 4; m++)
#pragma unroll
                for (int j = 0; j < 8; j++)
                    mma8(acc[m][j], a[m], bb[j][0], bb[j][1]);
        }
    }

    // epilogue
#pragma unroll
    for (int m = 0; m < 4; m++) {
        int row0 = bm + wm * 64 + m * 16 + g;
#pragma unroll
        for (int j = 0; j < 8; j++) {
            int col = bn + wn * 64 + j * 8 + 2 * tig;
            float b0 = bias[col], b1 = bias[col + 1];
            float v0 = acc[m][j][0] + b0, v1 = acc[m][j][1] + b1;
            float v2 = acc[m][j][2] + b0, v3 = acc[m][j][3] + b1;
            if (act == 1) {
                v0 = rna_tf32(tanhf(v0)); v1 = rna_tf32(tanhf(v1));
                v2 = rna_tf32(tanhf(v2)); v3 = rna_tf32(tanhf(v3));
            } else if (act == 2) {
                v0 = rna_tf32(v0); v1 = rna_tf32(v1);
                v2 = rna_tf32(v2); v3 = rna_tf32(v3);
            }
            *(float2*)&C[(size_t)row0 * DM + col] = make_float2(v0, v1);
            *(float2*)&C[(size_t)(row0 + 8) * DM + col] = make_float2(v2, v3);
        }
    }
}

// ---------------- tensor-core flash attention, 256-q blocks, 32-q warp tiles --------
// smem: Qs[256][68], Ps[256][68] (SEPARATE from Qs: Q is re-read every kt iter),
//       Ks 2x[64][68], Vs 2x[64][72]
#define FQS 68
#define FVS 72
#define FBM 256
#define FLASH_SMEM ((FBM * FQS * 2 + 2 * 64 * FQS + 2 * 64 * FVS) * 4)

__global__ void __launch_bounds__(256) flash_tc(
    const float* __restrict__ QF, const float* __restrict__ KF,
    const float* __restrict__ V, const int* __restrict__ mask,
    const float* __restrict__ temp, float* __restrict__ CTX) {
    extern __shared__ __align__(16) float sm[];
    float* Qs = sm;                          // 256 x FQS
    float* Ps = sm + FBM * FQS;              // 256 x FQS
    float* Ks = Ps + FBM * FQS;              // 2 x 64 x FQS
    float* Vs = Ks + 2 * 64 * FQS;           // 2 x 64 x FVS

    int tid = threadIdx.x;
    int warp = tid >> 5, lane = tid & 31;
    int g = lane >> 2, tig = lane & 3;
    int q0 = blockIdx.x * FBM, h = blockIdx.y, b = blockIdx.z;
    int rw = warp * 32;   // warp's 32 q-rows

    // load Q tile: 16 float4/thread
#pragma unroll
    for (int i = 0; i < 16; i++) {
        int idx = tid + 256 * i;
        int r = idx >> 4, d4 = (idx & 15) << 2;
        *(float4*)&Qs[r * FQS + d4] =
            *(const float4*)&QF[(size_t)(b * SEQ + q0 + r) * DM + h * DK + d4];
    }

    // K/V loader coords
    int lr[4], ld4[4];
#pragma unroll
    for (int i = 0; i < 4; i++) {
        int idx = tid + 256 * i;
        lr[i] = idx >> 4;  ld4[i] = (idx & 15) << 2;
    }

    float scale = 0.125f / temp[h];
    float mr[4], lsum[4];
#pragma unroll
    for (int t = 0; t < 4; t++) { mr[t] = -1e30f; lsum[t] = 0.f; }
    float acc[8][8];
#pragma unroll
    for (int j = 0; j < 8; j++)
#pragma unroll
        for (int t = 0; t < 8; t++) acc[j][t] = 0.f;

    // prologue: stage kt=0
#pragma unroll
    for (int i = 0; i < 4; i++) {
        size_t src = (size_t)(b * SEQ + lr[i]) * DM + h * DK + ld4[i];
        cp16(&Ks[lr[i] * FQS + ld4[i]], &KF[src]);
        cp16(&Vs[lr[i] * FVS + ld4[i]], &V[src]);
    }
    cp_commit();
    __syncthreads();   // Q tile visible to all warps

    const int NKT = SEQ / 64;
    for (int kt = 0; kt < NKT; kt++) {
        int buf = kt & 1;
        float* Kb = Ks + buf * 64 * FQS;
        float* Vb = Vs + buf * 64 * FVS;
        __syncthreads();
        if (kt + 1 < NKT) {
            float* Kn = Ks + (buf ^ 1) * 64 * FQS;
            float* Vn = Vs + (buf ^ 1) * 64 * FVS;
#pragma unroll
            for (int i = 0; i < 4; i++) {
                size_t src = (size_t)(b * SEQ + (kt + 1) * 64 + lr[i]) * DM + h * DK + ld4[i];
                cp16(&Kn[lr[i] * FQS + ld4[i]], &KF[src]);
                cp16(&Vn[lr[i] * FVS + ld4[i]], &V[src]);
            }
            cp_commit();
            cp_wait<1>();
        } else {
            cp_wait<0>();
        }
        __syncthreads();

        // S = Qf @ Kf^T  (32 q-rows per warp)
        float sD[8][8];
#pragma unroll
        for (int j = 0; j < 8; j++)
#pragma unroll
            for (int t = 0; t < 8; t++) sD[j][t] = 0.f;
#pragma unroll
        for (int s = 0; s < 8; s++) {
            unsigned qa[8];
            qa[0] = __float_as_uint(Qs[(rw + g) * FQS + 8 * s + tig]);
            qa[1] = __float_as_uint(Qs[(rw + g + 8) * FQS + 8 * s + tig]);
            qa[2] = __float_as_uint(Qs[(rw + g) * FQS + 8 * s + tig + 4]);
            qa[3] = __float_as_uint(Qs[(rw + g + 8) * FQS + 8 * s + tig + 4]);
            qa[4] = __float_as_uint(Qs[(rw + g + 16) * FQS + 8 * s + tig]);
            qa[5] = __float_as_uint(Qs[(rw + g + 24) * FQS + 8 * s + tig]);
            qa[6] = __float_as_uint(Qs[(rw + g + 16) * FQS + 8 * s + tig + 4]);
            qa[7] = __float_as_uint(Qs[(rw + g + 24) * FQS + 8 * s + tig + 4]);
#pragma unroll
            for (int j = 0; j < 8; j++) {
                unsigned b0 = __float_as_uint(Kb[(8 * j + g) * FQS + 8 * s + tig]);
                unsigned b1 = __float_as_uint(Kb[(8 * j + g) * FQS + 8 * s + tig + 4]);
                mma8(&sD[j][0], qa, b0, b1);
                mma8(&sD[j][4], qa + 4, b0, b1);
            }
        }

        // scale + mask (4 q-rows per thread: rw+g+8t)
#pragma unroll
        for (int j = 0; j < 8; j++) {
            int c = kt * 64 + 8 * j + 2 * tig;
#pragma unroll
            for (int t = 0; t < 4; t++) {
                int2 mv = *(const int2*)&mask[(size_t)(q0 + rw + g + 8 * t) * SEQ + c];
                sD[j][2 * t]     = mv.x ? sD[j][2 * t] * scale : -1e9f;
                sD[j][2 * t + 1] = mv.y ? sD[j][2 * t + 1] * scale : -1e9f;
            }
        }

        // online softmax, 4 rows per thread
        float mx[4];
#pragma unroll
        for (int t = 0; t < 4; t++) mx[t] = -1e30f;
#pragma unroll
        for (int j = 0; j < 8; j++)
#pragma unroll
            for (int t = 0; t < 4; t++)
                mx[t] = fmaxf(mx[t], fmaxf(sD[j][2 * t], sD[j][2 * t + 1]));
#pragma unroll
        for (int t = 0; t < 4; t++) {
            mx[t] = fmaxf(mx[t], __shfl_xor_sync(0xffffffffu, mx[t], 1));
            mx[t] = fmaxf(mx[t], __shfl_xor_sync(0xffffffffu, mx[t], 2));
        }
        float corr[4];
#pragma unroll
        for (int t = 0; t < 4; t++) {
            float nm = fmaxf(mr[t], mx[t]);
            corr[t] = __expf(mr[t] - nm);
            mr[t] = nm;
        }
        float ss[4] = {0.f, 0.f, 0.f, 0.f};
#pragma unroll
        for (int j = 0; j < 8; j++) {
#pragma unroll
            for (int t = 0; t < 4; t++) {
                float p0 = __expf(sD[j][2 * t] - mr[t]);
                float p1 = __expf(sD[j][2 * t + 1] - mr[t]);
                ss[t] += p0 + p1;
                *(float2*)&Ps[(rw + g + 8 * t) * FQS + 8 * j + 2 * tig] =
                    make_float2(rna_tf32(p0), rna_tf32(p1));
            }
        }
#pragma unroll
        for (int t = 0; t < 4; t++) {
            ss[t] += __shfl_xor_sync(0xffffffffu, ss[t], 1);
            ss[t] += __shfl_xor_sync(0xffffffffu, ss[t], 2);
            lsum[t] = lsum[t] * corr[t] + ss[t];
        }
#pragma unroll
        for (int j = 0; j < 8; j++) {
            acc[j][0] *= corr[0]; acc[j][1] *= corr[0];
            acc[j][2] *= corr[1]; acc[j][3] *= corr[1];
            acc[j][4] *= corr[2]; acc[j][5] *= corr[2];
            acc[j][6] *= corr[3]; acc[j][7] *= corr[3];
        }
        __syncwarp();   // Ps rows rw..rw+31 produced & consumed within same warp

        // ctx += P @ V
#pragma unroll
        for (int s = 0; s < 8; s++) {
            unsigned pa[8];
            pa[0] = __float_as_uint(Ps[(rw + g) * FQS + 8 * s + tig]);
            pa[1] = __float_as_uint(Ps[(rw + g + 8) * FQS + 8 * s + tig]);
            pa[2] = __float_as_uint(Ps[(rw + g) * FQS + 8 * s + tig + 4]);
            pa[3] = __float_as_uint(Ps[(rw + g + 8) * FQS + 8 * s + tig + 4]);
            pa[4] = __float_as_uint(Ps[(rw + g + 16) * FQS + 8 * s + tig]);
            pa[5] = __float_as_uint(Ps[(rw + g + 24) * FQS + 8 * s + tig]);
            pa[6] = __float_as_uint(Ps[(rw + g + 16) * FQS + 8 * s + tig + 4]);
            pa[7] = __float_as_uint(Ps[(rw + g + 24) * FQS + 8 * s + tig + 4]);
#pragma unroll
            for (int j = 0; j < 8; j++) {
                unsigned b0 = __float_as_uint(Vb[(8 * s + tig) * FVS + 8 * j + g]);
                unsigned b1 = __float_as_uint(Vb[(8 * s + tig + 4) * FVS + 8 * j + g]);
                mma8(&acc[j][0], pa, b0, b1);
                mma8(&acc[j][4], pa + 4, b0, b1);
            }
        }
    }

    // epilogue (tf32-round: CTX feeds out-proj GEMM)
    float inv[4];
#pragma unroll
    for (int t = 0; t < 4; t++) inv[t] = 1.0f / lsum[t];
#pragma unroll
    for (int j = 0; j < 8; j++) {
        int col = h * DK + 8 * j + 2 * tig;
#pragma unroll
        for (int t = 0; t < 4; t++) {
            *(float2*)&CTX[(size_t)(b * SEQ + q0 + rw + g + 8 * t) * DM + col] =
                make_float2(rna_tf32(acc[j][2 * t] * inv[t]),
                            rna_tf32(acc[j][2 * t + 1] * inv[t]));
        }
    }
}

// ---------------- in-place RMSNorm ----------------
__global__ void __launch_bounds__(256) rmsnorm_kernel(float* __restrict__ out,
                                                      const float* __restrict__ gamma) {
    int row = blockIdx.x;
    int tid = threadIdx.x;
    float4 x = *(const float4*)&out[(size_t)row * DM + (tid << 2)];
    float ss = x.x * x.x + x.y * x.y + x.z * x.z + x.w * x.w;
    __shared__ float red[8];
#pragma unroll
    for (int o = 16; o > 0; o >>= 1) ss += __shfl_xor_sync(0xffffffffu, ss, o);
    if ((tid & 31) == 0) red[tid >> 5] = ss;
    __syncthreads();
    if (tid < 8) {
        float sv = red[tid];
#pragma unroll
        for (int o = 4; o > 0; o >>= 1) sv += __shfl_xor_sync(0xffu, sv, o);
        if (tid == 0) red[0] = sv;
    }
    __syncthreads();
    float rms = rsqrtf(red[0] * (1.0f / (float)DM) + 1e-6f);
    float4 g = *(const float4*)&gamma[tid << 2];
    x.x *= rms * g.x; x.y *= rms * g.y; x.z *= rms * g.z; x.w *= rms * g.w;
    *(float4*)&out[(size_t)row * DM + (tid << 2)] = x;
}

// ---------------- launch ----------------
extern "C" void kernel_launch(void* const* d_in, const int* in_sizes, int n_in,
                              void* d_out, int out_size) {
    (void)in_sizes; (void)n_in; (void)out_size;
    const float* Q    = (const float*)d_in[0];
    const float* K    = (const float*)d_in[1];
    const float* V    = (const float*)d_in[2];
    const int*   mask = (const int*)d_in[3];
    const float* wq   = (const float*)d_in[4];
    const float* bq   = (const float*)d_in[5];
    const float* wk   = (const float*)d_in[6];
    const float* bk   = (const float*)d_in[7];
    const float* wv   = (const float*)d_in[8];
    const float* bv   = (const float*)d_in[9];
    const float* wo   = (const float*)d_in[10];
    const float* bo   = (const float*)d_in[11];
    const float* wnq  = (const float*)d_in[12];
    const float* bnq  = (const float*)d_in[13];
    const float* wnk  = (const float*)d_in[14];
    const float* bnk  = (const float*)d_in[15];
    const float* temp = (const float*)d_in[16];
    const float* gamma= (const float*)d_in[17];
    float* out = (float*)d_out;

    float *WQP, *WKP, *WVR, *WOR, *BQP, *BKP, *QR, *KR, *VR, *QFp, *KFp, *VPp, *CTXp;
    cudaGetSymbolAddress((void**)&WQP, g_WQP);
    cudaGetSymbolAddress((void**)&WKP, g_WKP);
    cudaGetSymbolAddress((void**)&WVR, g_WVR);
    cudaGetSymbolAddress((void**)&WOR, g_WOR);
    cudaGetSymbolAddress((void**)&BQP, g_BQP);
    cudaGetSymbolAddress((void**)&BKP, g_BKP);
    cudaGetSymbolAddress((void**)&QR, g_QR);
    cudaGetSymbolAddress((void**)&KR, g_KR);
    cudaGetSymbolAddress((void**)&VR, g_VR);
    cudaGetSymbolAddress((void**)&QFp, g_QF);
    cudaGetSymbolAddress((void**)&KFp, g_KF);
    cudaGetSymbolAddress((void**)&VPp, g_VP);
    cudaGetSymbolAddress((void**)&CTXp, g_CTX);

    cudaFuncSetAttribute(gemm_tc, cudaFuncAttributeMaxDynamicSharedMemorySize, GEMM_SMEM);
    cudaFuncSetAttribute(flash_tc, cudaFuncAttributeMaxDynamicSharedMemorySize, FLASH_SMEM);

    // prepass: tf32-round GEMM A/W operands
    round_copy<<<512, 256>>>(Q, QR, NTOK * DM / 4);
    round_copy<<<512, 256>>>(K, KR, NTOK * DM / 4);
    round_copy<<<512, 256>>>(V, VR, NTOK * DM / 4);
    round_copy<<<512, 256>>>(wv, WVR, DM * DM / 4);
    round_copy<<<512, 256>>>(wo, WOR, DM * DM / 4);

    fold_weights<<<DM * DM / 256, 256>>>(wq, bq, wnq, bnq, WQP, BQP);
    fold_weights<<<DM * DM / 256, 256>>>(wk, bk, wnk, bnk, WKP, BKP);

    dim3 ggrid(DM / GBN, NTOK / GBM);
    gemm_tc<<<ggrid, 256, GEMM_SMEM>>>(QR, WQP, BQP, QFp, 1);
    gemm_tc<<<ggrid, 256, GEMM_SMEM>>>(KR, WKP, BKP, KFp, 1);
    gemm_tc<<<ggrid, 256, GEMM_SMEM>>>(VR, WVR, bv, VPp, 2);

    dim3 agrid(SEQ / FBM, NH, 2);
    flash_tc<<<agrid, 256, FLASH_SMEM>>>(QFp, KFp, VPp, mask, temp, CTXp);

    gemm_tc<<<ggrid, 256, GEMM_SMEM>>>(CTXp, WOR, bo, out, 0);
    rmsnorm_kernel<<<NTOK, 256>>>(out, gamma);
}

// round 7
// speedup vs baseline: 1.0110x; 1.0110x over previous
#include <cuda_runtime.h>
#include <math.h>

#define DM 1024
#define NH 16
#define DK 64
#define SEQ 2048
#define NTOK 4096   // B * SEQ
#define NKT32 (SEQ / 64)   // packed-mask words per row

// ---------------- scratch (device globals) ----------------
__device__ float g_WQP[DM * DM];
__device__ float g_WKP[DM * DM];
__device__ float g_WVR[DM * DM];
__device__ float g_WOR[DM * DM];
__device__ float g_BQP[DM];
__device__ float g_BKP[DM];
__device__ float g_QR[NTOK * DM];
__device__ float g_KR[NTOK * DM];
__device__ float g_VR[NTOK * DM];
__device__ float g_QF[NTOK * DM];
__device__ float g_KF[NTOK * DM];
__device__ float g_VP[NTOK * DM];
__device__ float g_CTX[NTOK * DM];
__device__ unsigned long long g_PM[SEQ * NKT32];   // packed mask bits

// ---------------- helpers ----------------
__device__ __forceinline__ float rna_tf32(float x) {
    unsigned u;
    asm("cvt.rna.tf32.f32 %0, %1;" : "=r"(u) : "f"(x));
    return __uint_as_float(u);
}

__device__ __forceinline__ void mma8(float* c, const unsigned* a, unsigned b0, unsigned b1) {
    asm volatile(
        "mma.sync.aligned.m16n8k8.row.col.f32.tf32.tf32.f32 "
        "{%0,%1,%2,%3},{%4,%5,%6,%7},{%8,%9},{%0,%1,%2,%3};"
        : "+f"(c[0]), "+f"(c[1]), "+f"(c[2]), "+f"(c[3])
        : "r"(a[0]), "r"(a[1]), "r"(a[2]), "r"(a[3]), "r"(b0), "r"(b1));
}

__device__ __forceinline__ void cp16(float* dst_smem, const float* src) {
    unsigned s = (unsigned)__cvta_generic_to_shared(dst_smem);
    asm volatile("cp.async.cg.shared.global [%0], [%1], 16;\n" :: "r"(s), "l"(src));
}
__device__ __forceinline__ void cp_commit() {
    asm volatile("cp.async.commit_group;\n");
}
template <int N>
__device__ __forceinline__ void cp_wait() {
    asm volatile("cp.async.wait_group %0;\n" :: "n"(N));
}

// ---------------- prepass: tf32-round a tensor ----------------
__global__ void round_copy(const float* __restrict__ src, float* __restrict__ dst, int n4) {
    int stride = gridDim.x * blockDim.x;
    for (int i = blockIdx.x * blockDim.x + threadIdx.x; i < n4; i += stride) {
        float4 v = *(const float4*)&src[(size_t)i << 2];
        v.x = rna_tf32(v.x); v.y = rna_tf32(v.y);
        v.z = rna_tf32(v.z); v.w = rna_tf32(v.w);
        *(float4*)&dst[(size_t)i << 2] = v;
    }
}

// ---------------- prepass: pack int32 mask row-major into 64-bit words --------------
__global__ void pack_mask(const int* __restrict__ mask, unsigned long long* __restrict__ pm) {
    int idx = blockIdx.x * blockDim.x + threadIdx.x;   // q * NKT32 + kt
    if (idx >= SEQ * NKT32) return;
    int q = idx / NKT32, kt = idx % NKT32;
    const int* src = mask + (size_t)q * SEQ + kt * 64;
    unsigned long long bits = 0ull;
#pragma unroll
    for (int i = 0; i < 16; i++) {
        int4 v = *(const int4*)(src + 4 * i);
        unsigned long long b = (unsigned long long)((v.x ? 1u : 0u) | (v.y ? 2u : 0u) |
                                                    (v.z ? 4u : 0u) | (v.w ? 8u : 0u));
        bits |= b << (4 * i);
    }
    pm[idx] = bits;
}

// ---------------- fold per-head feature-map weights into projection ----------------
__global__ void fold_weights(const float* __restrict__ w, const float* __restrict__ b,
                             const float* __restrict__ wn, const float* __restrict__ bn,
                             float* __restrict__ wout, float* __restrict__ bout) {
    int idx = blockIdx.x * blockDim.x + threadIdx.x;
    if (idx >= DM * DM) return;
    int i = idx >> 10;
    int j = idx & 1023;
    int h = j >> 6, jj = j & 63;
    const float* wrow = w + i * DM + h * DK;
    float acc = 0.f;
#pragma unroll 8
    for (int d = 0; d < DK; d++) acc += wrow[d] * wn[d * DK + jj];
    wout[idx] = rna_tf32(acc);
    if (i == 0) {
        float bb = bn[jj];
        for (int d = 0; d < DK; d++) bb += b[h * DK + d] * wn[d * DK + jj];
        bout[j] = bb;
    }
}

// ---------------- tf32 TC GEMM, cp.async double-buffered (r5, unchanged) -------------
#define GBM 128
#define GBN 256
#define GBK 32
#define GAS 36
#define GBS 264
#define GEMM_SMEM ((2 * GBM * GAS + 2 * GBK * GBS) * 4)

__global__ void __launch_bounds__(256) gemm_tc(
    const float* __restrict__ A, const float* __restrict__ W,
    const float* __restrict__ bias, float* __restrict__ C, int act) {
    extern __shared__ __align__(16) float sg[];
    float* As = sg;                       // [2][128][36]
    float* Bs = sg + 2 * GBM * GAS;       // [2][32][264]

    int tid = threadIdx.x;
    int warp = tid >> 5, lane = tid & 31;
    int g = lane >> 2, tig = lane & 3;
    int wm = warp >> 2, wn = warp & 3;
    int bm = blockIdx.y * GBM, bn = blockIdx.x * GBN;

    int ar[4], ak[4], bkr[8], bn4[8];
#pragma unroll
    for (int i = 0; i < 4; i++) {
        int idx = tid + 256 * i;
        ar[i] = idx >> 3;  ak[i] = (idx & 7) << 2;
    }
#pragma unroll
    for (int i = 0; i < 8; i++) {
        int idx = tid + 256 * i;
        bkr[i] = idx >> 6;  bn4[i] = (idx & 63) << 2;
    }

    float acc[4][8][4];
#pragma unroll
    for (int m = 0; m < 4; m++)
#pragma unroll
        for (int j = 0; j < 8; j++)
#pragma unroll
            for (int t = 0; t < 4; t++) acc[m][j][t] = 0.f;

#pragma unroll
    for (int i = 0; i < 4; i++)
        cp16(&As[ar[i] * GAS + ak[i]], &A[(size_t)(bm + ar[i]) * DM + ak[i]]);
#pragma unroll
    for (int i = 0; i < 8; i++)
        cp16(&Bs[bkr[i] * GBS + bn4[i]], &W[(size_t)bkr[i] * DM + bn + bn4[i]]);
    cp_commit();

    const int NK = DM / GBK;
    for (int kt = 0; kt < NK; kt++) {
        int buf = kt & 1;
        float* Ab = As + buf * GBM * GAS;
        float* Bb = Bs + buf * GBK * GBS;
        __syncthreads();
        if (kt + 1 < NK) {
            int k0n = (kt + 1) * GBK;
            float* An = As + (buf ^ 1) * GBM * GAS;
            float* Bn = Bs + (buf ^ 1) * GBK * GBS;
#pragma unroll
            for (int i = 0; i < 4; i++)
                cp16(&An[ar[i] * GAS + ak[i]], &A[(size_t)(bm + ar[i]) * DM + k0n + ak[i]]);
#pragma unroll
            for (int i = 0; i < 8; i++)
                cp16(&Bn[bkr[i] * GBS + bn4[i]], &W[(size_t)(k0n + bkr[i]) * DM + bn + bn4[i]]);
            cp_commit();
            cp_wait<1>();
        } else {
            cp_wait<0>();
        }
        __syncthreads();

#pragma unroll
        for (int s = 0; s < 4; s++) {
            unsigned a[4][4], bb[8][2];
#pragma unroll
            for (int m = 0; m < 4; m++) {
                int m0 = wm * 64 + m * 16;
                a[m][0] = __float_as_uint(Ab[(m0 + g) * GAS + 8 * s + tig]);
                a[m][1] = __float_as_uint(Ab[(m0 + g + 8) * GAS + 8 * s + tig]);
                a[m][2] = __float_as_uint(Ab[(m0 + g) * GAS + 8 * s + tig + 4]);
                a[m][3] = __float_as_uint(Ab[(m0 + g + 8) * GAS + 8 * s + tig + 4]);
            }
#pragma unroll
            for (int j = 0; j < 8; j++) {
                int n0 = wn * 64 + j * 8;
                bb[j][0] = __float_as_uint(Bb[(8 * s + tig) * GBS + n0 + g]);
                bb[j][1] = __float_as_uint(Bb[(8 * s + tig + 4) * GBS + n0 + g]);
            }
#pragma unroll
            for (int m = 0; m < 4; m++)
#pragma unroll
                for (int j = 0; j < 8; j++)
                    mma8(acc[m][j], a[m], bb[j][0], bb[j][1]);
        }
    }

#pragma unroll
    for (int m = 0; m < 4; m++) {
        int row0 = bm + wm * 64 + m * 16 + g;
#pragma unroll
        for (int j = 0; j < 8; j++) {
            int col = bn + wn * 64 + j * 8 + 2 * tig;
            float b0 = bias[col], b1 = bias[col + 1];
            float v0 = acc[m][j][0] + b0, v1 = acc[m][j][1] + b1;
            float v2 = acc[m][j][2] + b0, v3 = acc[m][j][3] + b1;
            if (act == 1) {
                v0 = rna_tf32(tanhf(v0)); v1 = rna_tf32(tanhf(v1));
                v2 = rna_tf32(tanhf(v2)); v3 = rna_tf32(tanhf(v3));
            } else if (act == 2) {
                v0 = rna_tf32(v0); v1 = rna_tf32(v1);
                v2 = rna_tf32(v2); v3 = rna_tf32(v3);
            }
            *(float2*)&C[(size_t)row0 * DM + col] = make_float2(v0, v1);
            *(float2*)&C[(size_t)(row0 + 8) * DM + col] = make_float2(v2, v3);
        }
    }
}

// ---------------- flash attention: no-max softmax + packed mask ----------------
// 256-q blocks, 8 warps x 32-q warp tiles, tf32 mma, cp.async x2-buffered K/V.
#define FQS 68
#define FVS 72
#define FBM 256
#define FLASH_SMEM ((FBM * FQS * 2 + 2 * 64 * FQS + 2 * 64 * FVS) * 4)

__global__ void __launch_bounds__(256) flash_tc(
    const float* __restrict__ QF, const float* __restrict__ KF,
    const float* __restrict__ V, const unsigned long long* __restrict__ pmask,
    const float* __restrict__ temp, float* __restrict__ CTX) {
    extern __shared__ __align__(16) float sm[];
    float* Qs = sm;                          // 256 x FQS
    float* Ps = sm + FBM * FQS;              // 256 x FQS
    float* Ks = Ps + FBM * FQS;              // 2 x 64 x FQS
    float* Vs = Ks + 2 * 64 * FQS;           // 2 x 64 x FVS

    int tid = threadIdx.x;
    int warp = tid >> 5, lane = tid & 31;
    int g = lane >> 2, tig = lane & 3;
    int q0 = blockIdx.x * FBM, h = blockIdx.y, b = blockIdx.z;
    int rw = warp * 32;

#pragma unroll
    for (int i = 0; i < 16; i++) {
        int idx = tid + 256 * i;
        int r = idx >> 4, d4 = (idx & 15) << 2;
        *(float4*)&Qs[r * FQS + d4] =
            *(const float4*)&QF[(size_t)(b * SEQ + q0 + r) * DM + h * DK + d4];
    }

    int lr[4], ld4[4];
#pragma unroll
    for (int i = 0; i < 4; i++) {
        int idx = tid + 256 * i;
        lr[i] = idx >> 4;  ld4[i] = (idx & 15) << 2;
    }

    // fold log2e into score scale -> exp2f needs no extra multiply
    float scale2 = (0.125f / temp[h]) * 1.44269504088896f;
    float lsum[4] = {0.f, 0.f, 0.f, 0.f};
    float acc[8][8];
#pragma unroll
    for (int j = 0; j < 8; j++)
#pragma unroll
        for (int t = 0; t < 8; t++) acc[j][t] = 0.f;

#pragma unroll
    for (int i = 0; i < 4; i++) {
        size_t src = (size_t)(b * SEQ + lr[i]) * DM + h * DK + ld4[i];
        cp16(&Ks[lr[i] * FQS + ld4[i]], &KF[src]);
        cp16(&Vs[lr[i] * FVS + ld4[i]], &V[src]);
    }
    cp_commit();
    __syncthreads();

    const int NKT = SEQ / 64;
    for (int kt = 0; kt < NKT; kt++) {
        int buf = kt & 1;
        float* Kb = Ks + buf * 64 * FQS;
        float* Vb = Vs + buf * 64 * FVS;
        __syncthreads();
        if (kt + 1 < NKT) {
            float* Kn = Ks + (buf ^ 1) * 64 * FQS;
            float* Vn = Vs + (buf ^ 1) * 64 * FVS;
#pragma unroll
            for (int i = 0; i < 4; i++) {
                size_t src = (size_t)(b * SEQ + (kt + 1) * 64 + lr[i]) * DM + h * DK + ld4[i];
                cp16(&Kn[lr[i] * FQS + ld4[i]], &KF[src]);
                cp16(&Vn[lr[i] * FVS + ld4[i]], &V[src]);
            }
            cp_commit();
            cp_wait<1>();
        } else {
            cp_wait<0>();
        }
        __syncthreads();

        // S = Qf @ Kf^T  (32 q-rows per warp)
        float sD[8][8];
#pragma unroll
        for (int j = 0; j < 8; j++)
#pragma unroll
            for (int t = 0; t < 8; t++) sD[j][t] = 0.f;
#pragma unroll
        for (int s = 0; s < 8; s++) {
            unsigned qa[8];
            qa[0] = __float_as_uint(Qs[(rw + g) * FQS + 8 * s + tig]);
            qa[1] = __float_as_uint(Qs[(rw + g + 8) * FQS + 8 * s + tig]);
            qa[2] = __float_as_uint(Qs[(rw + g) * FQS + 8 * s + tig + 4]);
            qa[3] = __float_as_uint(Qs[(rw + g + 8) * FQS + 8 * s + tig + 4]);
            qa[4] = __float_as_uint(Qs[(rw + g + 16) * FQS + 8 * s + tig]);
            qa[5] = __float_as_uint(Qs[(rw + g + 24) * FQS + 8 * s + tig]);
            qa[6] = __float_as_uint(Qs[(rw + g + 16) * FQS + 8 * s + tig + 4]);
            qa[7] = __float_as_uint(Qs[(rw + g + 24) * FQS + 8 * s + tig + 4]);
#pragma unroll
            for (int j = 0; j < 8; j++) {
                unsigned b0 = __float_as_uint(Kb[(8 * j + g) * FQS + 8 * s + tig]);
                unsigned b1 = __float_as_uint(Kb[(8 * j + g) * FQS + 8 * s + tig + 4]);
                mma8(&sD[j][0], qa, b0, b1);
                mma8(&sD[j][4], qa + 4, b0, b1);
            }
        }

        // packed mask for this tile: one u64 per q-row owned by this thread
        unsigned long long m64[4];
#pragma unroll
        for (int t = 0; t < 4; t++)
            m64[t] = pmask[(size_t)(q0 + rw + g + 8 * t) * NKT32 + kt];

        // softmax without running max (|score*log2e| <= 11.6 -> exp2 safe in fp32)
#pragma unroll
        for (int j = 0; j < 8; j++) {
#pragma unroll
            for (int t = 0; t < 4; t++) {
                unsigned pair = (unsigned)(m64[t] >> (8 * j + 2 * tig)) & 3u;
                float e0 = exp2f(sD[j][2 * t] * scale2);
                float e1 = exp2f(sD[j][2 * t + 1] * scale2);
                float p0 = (pair & 1u) ? rna_tf32(e0) : 0.f;
                float p1 = (pair & 2u) ? rna_tf32(e1) : 0.f;
                lsum[t] += p0 + p1;   // sum of ROUNDED p: normalization cancels rounding bias
                *(float2*)&Ps[(rw + g + 8 * t) * FQS + 8 * j + 2 * tig] = make_float2(p0, p1);
            }
        }
        __syncwarp();   // Ps rows rw..rw+31 produced & consumed within same warp

        // ctx += P @ V
#pragma unroll
        for (int s = 0; s < 8; s++) {
            unsigned pa[8];
            pa[0] = __float_as_uint(Ps[(rw + g) * FQS + 8 * s + tig]);
            pa[1] = __float_as_uint(Ps[(rw + g + 8) * FQS + 8 * s + tig]);
            pa[2] = __float_as_uint(Ps[(rw + g) * FQS + 8 * s + tig + 4]);
            pa[3] = __float_as_uint(Ps[(rw + g + 8) * FQS + 8 * s + tig + 4]);
            pa[4] = __float_as_uint(Ps[(rw + g + 16) * FQS + 8 * s + tig]);
            pa[5] = __float_as_uint(Ps[(rw + g + 24) * FQS + 8 * s + tig]);
            pa[6] = __float_as_uint(Ps[(rw + g + 16) * FQS + 8 * s + tig + 4]);
            pa[7] = __float_as_uint(Ps[(rw + g + 24) * FQS + 8 * s + tig + 4]);
#pragma unroll
            for (int j = 0; j < 8; j++) {
                unsigned b0 = __float_as_uint(Vb[(8 * s + tig) * FVS + 8 * j + g]);
                unsigned b1 = __float_as_uint(Vb[(8 * s + tig + 4) * FVS + 8 * j + g]);
                mma8(&acc[j][0], pa, b0, b1);
                mma8(&acc[j][4], pa + 4, b0, b1);
            }
        }
    }

    // single final reduce of row sums across the quad
#pragma unroll
    for (int t = 0; t < 4; t++) {
        lsum[t] += __shfl_xor_sync(0xffffffffu, lsum[t], 1);
        lsum[t] += __shfl_xor_sync(0xffffffffu, lsum[t], 2);
    }

    float inv[4];
#pragma unroll
    for (int t = 0; t < 4; t++) inv[t] = 1.0f / lsum[t];
#pragma unroll
    for (int j = 0; j < 8; j++) {
        int col = h * DK + 8 * j + 2 * tig;
#pragma unroll
        for (int t = 0; t < 4; t++) {
            *(float2*)&CTX[(size_t)(b * SEQ + q0 + rw + g + 8 * t) * DM + col] =
                make_float2(rna_tf32(acc[j][2 * t] * inv[t]),
                            rna_tf32(acc[j][2 * t + 1] * inv[t]));
        }
    }
}

// ---------------- in-place RMSNorm ----------------
__global__ void __launch_bounds__(256) rmsnorm_kernel(float* __restrict__ out,
                                                      const float* __restrict__ gamma) {
    int row = blockIdx.x;
    int tid = threadIdx.x;
    float4 x = *(const float4*)&out[(size_t)row * DM + (tid << 2)];
    float ss = x.x * x.x + x.y * x.y + x.z * x.z + x.w * x.w;
    __shared__ float red[8];
#pragma unroll
    for (int o = 16; o > 0; o >>= 1) ss += __shfl_xor_sync(0xffffffffu, ss, o);
    if ((tid & 31) == 0) red[tid >> 5] = ss;
    __syncthreads();
    if (tid < 8) {
        float sv = red[tid];
#pragma unroll
        for (int o = 4; o > 0; o >>= 1) sv += __shfl_xor_sync(0xffu, sv, o);
        if (tid == 0) red[0] = sv;
    }
    __syncthreads();
    float rms = rsqrtf(red[0] * (1.0f / (float)DM) + 1e-6f);
    float4 g = *(const float4*)&gamma[tid << 2];
    x.x *= rms * g.x; x.y *= rms * g.y; x.z *= rms * g.z; x.w *= rms * g.w;
    *(float4*)&out[(size_t)row * DM + (tid << 2)] = x;
}

// ---------------- launch ----------------
extern "C" void kernel_launch(void* const* d_in, const int* in_sizes, int n_in,
                              void* d_out, int out_size) {
    (void)in_sizes; (void)n_in; (void)out_size;
    const float* Q    = (const float*)d_in[0];
    const float* K    = (const float*)d_in[1];
    const float* V    = (const float*)d_in[2];
    const int*   mask = (const int*)d_in[3];
    const float* wq   = (const float*)d_in[4];
    const float* bq   = (const float*)d_in[5];
    const float* wk   = (const float*)d_in[6];
    const float* bk   = (const float*)d_in[7];
    const float* wv   = (const float*)d_in[8];
    const float* bv   = (const float*)d_in[9];
    const float* wo   = (const float*)d_in[10];
    const float* bo   = (const float*)d_in[11];
    const float* wnq  = (const float*)d_in[12];
    const float* bnq  = (const float*)d_in[13];
    const float* wnk  = (const float*)d_in[14];
    const float* bnk  = (const float*)d_in[15];
    const float* temp = (const float*)d_in[16];
    const float* gamma= (const float*)d_in[17];
    float* out = (float*)d_out;

    float *WQP, *WKP, *WVR, *WOR, *BQP, *BKP, *QR, *KR, *VR, *QFp, *KFp, *VPp, *CTXp;
    unsigned long long* PM;
    cudaGetSymbolAddress((void**)&WQP, g_WQP);
    cudaGetSymbolAddress((void**)&WKP, g_WKP);
    cudaGetSymbolAddress((void**)&WVR, g_WVR);
    cudaGetSymbolAddress((void**)&WOR, g_WOR);
    cudaGetSymbolAddress((void**)&BQP, g_BQP);
    cudaGetSymbolAddress((void**)&BKP, g_BKP);
    cudaGetSymbolAddress((void**)&QR, g_QR);
    cudaGetSymbolAddress((void**)&KR, g_KR);
    cudaGetSymbolAddress((void**)&VR, g_VR);
    cudaGetSymbolAddress((void**)&QFp, g_QF);
    cudaGetSymbolAddress((void**)&KFp, g_KF);
    cudaGetSymbolAddress((void**)&VPp, g_VP);
    cudaGetSymbolAddress((void**)&CTXp, g_CTX);
    cudaGetSymbolAddress((void**)&PM, g_PM);

    cudaFuncSetAttribute(gemm_tc, cudaFuncAttributeMaxDynamicSharedMemorySize, GEMM_SMEM);
    cudaFuncSetAttribute(flash_tc, cudaFuncAttributeMaxDynamicSharedMemorySize, FLASH_SMEM);

    // prepasses
    round_copy<<<512, 256>>>(Q, QR, NTOK * DM / 4);
    round_copy<<<512, 256>>>(K, KR, NTOK * DM / 4);
    round_copy<<<512, 256>>>(V, VR, NTOK * DM / 4);
    round_copy<<<512, 256>>>(wv, WVR, DM * DM / 4);
    round_copy<<<512, 256>>>(wo, WOR, DM * DM / 4);
    pack_mask<<<(SEQ * NKT32 + 255) / 256, 256>>>(mask, PM);

    fold_weights<<<DM * DM / 256, 256>>>(wq, bq, wnq, bnq, WQP, BQP);
    fold_weights<<<DM * DM / 256, 256>>>(wk, bk, wnk, bnk, WKP, BKP);

    dim3 ggrid(DM / GBN, NTOK / GBM);
    gemm_tc<<<ggrid, 256, GEMM_SMEM>>>(QR, WQP, BQP, QFp, 1);
    gemm_tc<<<ggrid, 256, GEMM_SMEM>>>(KR, WKP, BKP, KFp, 1);
    gemm_tc<<<ggrid, 256, GEMM_SMEM>>>(VR, WVR, bv, VPp, 2);

    dim3 agrid(SEQ / FBM, NH, 2);
    flash_tc<<<agrid, 256, FLASH_SMEM>>>(QFp, KFp, VPp, PM, temp, CTXp);

    gemm_tc<<<ggrid, 256, GEMM_SMEM>>>(CTXp, WOR, bo, out, 0);
    rmsnorm_kernel<<<NTOK, 256>>>(out, gamma);
}

// round 8
// speedup vs baseline: 1.2157x; 1.2024x over previous
#include <cuda_runtime.h>
#include <math.h>

#define DM 1024
#define NH 16
#define DK 64
#define SEQ 2048
#define NTOK 4096   // B * SEQ
#define NKT32 (SEQ / 64)   // packed-mask words per row

// ---------------- scratch (device globals) ----------------
__device__ float g_WQP[DM * DM];
__device__ float g_WKP[DM * DM];
__device__ float g_WVR[DM * DM];
__device__ float g_WOR[DM * DM];
__device__ float g_BQP[DM];
__device__ float g_BKP[DM];
__device__ float g_QR[NTOK * DM];
__device__ float g_KR[NTOK * DM];
__device__ float g_VR[NTOK * DM];
__device__ float g_QF[NTOK * DM];
__device__ float g_KF[NTOK * DM];
__device__ float g_VP[NTOK * DM];
__device__ float g_CTX[NTOK * DM];
__device__ unsigned long long g_PM[SEQ * NKT32];

// ---------------- helpers ----------------
__device__ __forceinline__ float rna_tf32(float x) {
    unsigned u;
    asm("cvt.rna.tf32.f32 %0, %1;" : "=r"(u) : "f"(x));
    return __uint_as_float(u);
}
__device__ __forceinline__ float ex2(float x) {
    float r;
    asm("ex2.approx.f32 %0, %1;" : "=f"(r) : "f"(x));
    return r;
}

__device__ __forceinline__ void mma8(float* c, const unsigned* a, unsigned b0, unsigned b1) {
    asm volatile(
        "mma.sync.aligned.m16n8k8.row.col.f32.tf32.tf32.f32 "
        "{%0,%1,%2,%3},{%4,%5,%6,%7},{%8,%9},{%0,%1,%2,%3};"
        : "+f"(c[0]), "+f"(c[1]), "+f"(c[2]), "+f"(c[3])
        : "r"(a[0]), "r"(a[1]), "r"(a[2]), "r"(a[3]), "r"(b0), "r"(b1));
}

__device__ __forceinline__ void cp16(float* dst_smem, const float* src) {
    unsigned s = (unsigned)__cvta_generic_to_shared(dst_smem);
    asm volatile("cp.async.cg.shared.global [%0], [%1], 16;\n" :: "r"(s), "l"(src));
}
__device__ __forceinline__ void cp_commit() {
    asm volatile("cp.async.commit_group;\n");
}
template <int N>
__device__ __forceinline__ void cp_wait() {
    asm volatile("cp.async.wait_group %0;\n" :: "n"(N));
}

// ---------------- prepass: tf32-round tensors, z-batched ----------------
__global__ void round_copy3(const float* __restrict__ s0, float* __restrict__ d0,
                            const float* __restrict__ s1, float* __restrict__ d1,
                            const float* __restrict__ s2, float* __restrict__ d2, int n4) {
    const float* src = blockIdx.z == 0 ? s0 : (blockIdx.z == 1 ? s1 : s2);
    float* dst = blockIdx.z == 0 ? d0 : (blockIdx.z == 1 ? d1 : d2);
    int stride = gridDim.x * blockDim.x;
    for (int i = blockIdx.x * blockDim.x + threadIdx.x; i < n4; i += stride) {
        float4 v = *(const float4*)&src[(size_t)i << 2];
        v.x = rna_tf32(v.x); v.y = rna_tf32(v.y);
        v.z = rna_tf32(v.z); v.w = rna_tf32(v.w);
        *(float4*)&dst[(size_t)i << 2] = v;
    }
}

// ---------------- prepass: pack mask bits ----------------
__global__ void pack_mask(const int* __restrict__ mask, unsigned long long* __restrict__ pm) {
    int idx = blockIdx.x * blockDim.x + threadIdx.x;
    if (idx >= SEQ * NKT32) return;
    int q = idx / NKT32, kt = idx % NKT32;
    const int* src = mask + (size_t)q * SEQ + kt * 64;
    unsigned long long bits = 0ull;
#pragma unroll
    for (int i = 0; i < 16; i++) {
        int4 v = *(const int4*)(src + 4 * i);
        unsigned long long b = (unsigned long long)((v.x ? 1u : 0u) | (v.y ? 2u : 0u) |
                                                    (v.z ? 4u : 0u) | (v.w ? 8u : 0u));
        bits |= b << (4 * i);
    }
    pm[idx] = bits;
}

// ---------------- fold per-head feature-map weights ----------------
__global__ void fold_weights(const float* __restrict__ w, const float* __restrict__ b,
                             const float* __restrict__ wn, const float* __restrict__ bn,
                             float* __restrict__ wout, float* __restrict__ bout) {
    int idx = blockIdx.x * blockDim.x + threadIdx.x;
    if (idx >= DM * DM) return;
    int i = idx >> 10;
    int j = idx & 1023;
    int h = j >> 6, jj = j & 63;
    const float* wrow = w + i * DM + h * DK;
    float acc = 0.f;
#pragma unroll 8
    for (int d = 0; d < DK; d++) acc += wrow[d] * wn[d * DK + jj];
    wout[idx] = rna_tf32(acc);
    if (i == 0) {
        float bb = bn[jj];
        for (int d = 0; d < DK; d++) bb += b[h * DK + d] * wn[d * DK + jj];
        bout[j] = bb;
    }
}

// ---------------- tf32 TC GEMM, 3-stage cp.async pipeline ----------------
#define GBM 128
#define GBN 256
#define GBK 32
#define GAS 36
#define GBS 264
#define GST 3
#define GEMM_SMEM (GST * (GBM * GAS + GBK * GBS) * 4)

__device__ __forceinline__ void gemm_body(
    const float* __restrict__ A, const float* __restrict__ W,
    const float* __restrict__ bias, float* __restrict__ C, int act,
    float* sg, int bm, int bn) {
    float* As = sg;                         // [3][128][36]
    float* Bs = sg + GST * GBM * GAS;       // [3][32][264]

    int tid = threadIdx.x;
    int warp = tid >> 5, lane = tid & 31;
    int g = lane >> 2, tig = lane & 3;
    int wm = warp >> 2, wn = warp & 3;

    int ar[4], ak[4], bkr[8], bn4[8];
#pragma unroll
    for (int i = 0; i < 4; i++) {
        int idx = tid + 256 * i;
        ar[i] = idx >> 3;  ak[i] = (idx & 7) << 2;
    }
#pragma unroll
    for (int i = 0; i < 8; i++) {
        int idx = tid + 256 * i;
        bkr[i] = idx >> 6;  bn4[i] = (idx & 63) << 2;
    }

    float acc[4][8][4];
#pragma unroll
    for (int m = 0; m < 4; m++)
#pragma unroll
        for (int j = 0; j < 8; j++)
#pragma unroll
            for (int t = 0; t < 4; t++) acc[m][j][t] = 0.f;

#define GFILL(CK, BUF)                                                                  \
    do {                                                                                \
        int k0_ = (CK) * GBK;                                                           \
        float* An_ = As + (BUF) * GBM * GAS;                                            \
        float* Bn_ = Bs + (BUF) * GBK * GBS;                                            \
        _Pragma("unroll")                                                               \
        for (int i = 0; i < 4; i++)                                                     \
            cp16(&An_[ar[i] * GAS + ak[i]], &A[(size_t)(bm + ar[i]) * DM + k0_ + ak[i]]); \
        _Pragma("unroll")                                                               \
        for (int i = 0; i < 8; i++)                                                     \
            cp16(&Bn_[bkr[i] * GBS + bn4[i]], &W[(size_t)(k0_ + bkr[i]) * DM + bn + bn4[i]]); \
    } while (0)

    GFILL(0, 0); cp_commit();
    GFILL(1, 1); cp_commit();

    const int NK = DM / GBK;
    for (int kt = 0; kt < NK; kt++) {
        int buf = kt % GST;
        __syncthreads();   // all warps done compute kt-1 -> safe to overwrite buf (kt+2)%3
        if (kt + 2 < NK) {
            GFILL(kt + 2, (kt + 2) % GST);
            cp_commit();
            cp_wait<2>();
        } else if (kt + 1 < NK) {
            cp_wait<1>();
        } else {
            cp_wait<0>();
        }
        __syncthreads();

        float* Ab = As + buf * GBM * GAS;
        float* Bb = Bs + buf * GBK * GBS;
#pragma unroll
        for (int s = 0; s < 4; s++) {
            unsigned a[4][4], bb[8][2];
#pragma unroll
            for (int m = 0; m < 4; m++) {
                int m0 = wm * 64 + m * 16;
                a[m][0] = __float_as_uint(Ab[(m0 + g) * GAS + 8 * s + tig]);
                a[m][1] = __float_as_uint(Ab[(m0 + g + 8) * GAS + 8 * s + tig]);
                a[m][2] = __float_as_uint(Ab[(m0 + g) * GAS + 8 * s + tig + 4]);
                a[m][3] = __float_as_uint(Ab[(m0 + g + 8) * GAS + 8 * s + tig + 4]);
            }
#pragma unroll
            for (int j = 0; j < 8; j++) {
                int n0 = wn * 64 + j * 8;
                bb[j][0] = __float_as_uint(Bb[(8 * s + tig) * GBS + n0 + g]);
                bb[j][1] = __float_as_uint(Bb[(8 * s + tig + 4) * GBS + n0 + g]);
            }
#pragma unroll
            for (int m = 0; m < 4; m++)
#pragma unroll
                for (int j = 0; j < 8; j++)
                    mma8(acc[m][j], a[m], bb[j][0], bb[j][1]);
        }
    }
#undef GFILL

#pragma unroll
    for (int m = 0; m < 4; m++) {
        int row0 = bm + wm * 64 + m * 16 + g;
#pragma unroll
        for (int j = 0; j < 8; j++) {
            int col = bn + wn * 64 + j * 8 + 2 * tig;
            float b0 = bias[col], b1 = bias[col + 1];
            float v0 = acc[m][j][0] + b0, v1 = acc[m][j][1] + b1;
            float v2 = acc[m][j][2] + b0, v3 = acc[m][j][3] + b1;
            if (act == 1) {
                v0 = rna_tf32(tanhf(v0)); v1 = rna_tf32(tanhf(v1));
                v2 = rna_tf32(tanhf(v2)); v3 = rna_tf32(tanhf(v3));
            } else if (act == 2) {
                v0 = rna_tf32(v0); v1 = rna_tf32(v1);
                v2 = rna_tf32(v2); v3 = rna_tf32(v3);
            }
            *(float2*)&C[(size_t)row0 * DM + col] = make_float2(v0, v1);
            *(float2*)&C[(size_t)(row0 + 8) * DM + col] = make_float2(v2, v3);
        }
    }
}

// batched QKV projection (z selects operand set); act: Q=1 K=1 V=2
__global__ void __launch_bounds__(256) gemm_qkv(
    const float* __restrict__ A0, const float* __restrict__ W0, const float* __restrict__ b0, float* __restrict__ C0,
    const float* __restrict__ A1, const float* __restrict__ W1, const float* __restrict__ b1, float* __restrict__ C1,
    const float* __restrict__ A2, const float* __restrict__ W2, const float* __restrict__ b2, float* __restrict__ C2) {
    extern __shared__ __align__(16) float sg[];
    int z = blockIdx.z;
    const float* A = z == 0 ? A0 : (z == 1 ? A1 : A2);
    const float* W = z == 0 ? W0 : (z == 1 ? W1 : W2);
    const float* bias = z == 0 ? b0 : (z == 1 ? b1 : b2);
    float* C = z == 0 ? C0 : (z == 1 ? C1 : C2);
    int act = z == 2 ? 2 : 1;
    gemm_body(A, W, bias, C, act, sg, blockIdx.y * GBM, blockIdx.x * GBN);
}

__global__ void __launch_bounds__(256) gemm_tc(
    const float* __restrict__ A, const float* __restrict__ W,
    const float* __restrict__ bias, float* __restrict__ C, int act) {
    extern __shared__ __align__(16) float sg[];
    gemm_body(A, W, bias, C, act, sg, blockIdx.y * GBM, blockIdx.x * GBN);
}

// ---------------- flash attention: no-max softmax, packed mask, raw-P ----------------
#define FQS 68
#define FVS 72
#define FBM 256
#define FLASH_SMEM ((FBM * FQS * 2 + 2 * 64 * FQS + 2 * 64 * FVS) * 4)

__global__ void __launch_bounds__(256) flash_tc(
    const float* __restrict__ QF, const float* __restrict__ KF,
    const float* __restrict__ V, const unsigned long long* __restrict__ pmask,
    const float* __restrict__ temp, float* __restrict__ CTX) {
    extern __shared__ __align__(16) float sm[];
    float* Qs = sm;                          // 256 x FQS
    float* Ps = sm + FBM * FQS;              // 256 x FQS
    float* Ks = Ps + FBM * FQS;              // 2 x 64 x FQS
    float* Vs = Ks + 2 * 64 * FQS;           // 2 x 64 x FVS

    int tid = threadIdx.x;
    int warp = tid >> 5, lane = tid & 31;
    int g = lane >> 2, tig = lane & 3;
    int q0 = blockIdx.x * FBM, h = blockIdx.y, b = blockIdx.z;
    int rw = warp * 32;

#pragma unroll
    for (int i = 0; i < 16; i++) {
        int idx = tid + 256 * i;
        int r = idx >> 4, d4 = (idx & 15) << 2;
        *(float4*)&Qs[r * FQS + d4] =
            *(const float4*)&QF[(size_t)(b * SEQ + q0 + r) * DM + h * DK + d4];
    }

    int lr[4], ld4[4];
#pragma unroll
    for (int i = 0; i < 4; i++) {
        int idx = tid + 256 * i;
        lr[i] = idx >> 4;  ld4[i] = (idx & 15) << 2;
    }

    float scale2 = (0.125f / temp[h]) * 1.44269504088896f;   // log2e folded in
    float lsum[4] = {0.f, 0.f, 0.f, 0.f};
    float acc[8][8];
#pragma unroll
    for (int j = 0; j < 8; j++)
#pragma unroll
        for (int t = 0; t < 8; t++) acc[j][t] = 0.f;

#pragma unroll
    for (int i = 0; i < 4; i++) {
        size_t src = (size_t)(b * SEQ + lr[i]) * DM + h * DK + ld4[i];
        cp16(&Ks[lr[i] * FQS + ld4[i]], &KF[src]);
        cp16(&Vs[lr[i] * FVS + ld4[i]], &V[src]);
    }
    cp_commit();
    __syncthreads();

    const int NKT = SEQ / 64;
    for (int kt = 0; kt < NKT; kt++) {
        int buf = kt & 1;
        float* Kb = Ks + buf * 64 * FQS;
        float* Vb = Vs + buf * 64 * FVS;
        __syncthreads();
        if (kt + 1 < NKT) {
            float* Kn = Ks + (buf ^ 1) * 64 * FQS;
            float* Vn = Vs + (buf ^ 1) * 64 * FVS;
#pragma unroll
            for (int i = 0; i < 4; i++) {
                size_t src = (size_t)(b * SEQ + (kt + 1) * 64 + lr[i]) * DM + h * DK + ld4[i];
                cp16(&Kn[lr[i] * FQS + ld4[i]], &KF[src]);
                cp16(&Vn[lr[i] * FVS + ld4[i]], &V[src]);
            }
            cp_commit();
            cp_wait<1>();
        } else {
            cp_wait<0>();
        }
        __syncthreads();

        // S = Qf @ Kf^T  (32 q-rows per warp)
        float sD[8][8];
#pragma unroll
        for (int j = 0; j < 8; j++)
#pragma unroll
            for (int t = 0; t < 8; t++) sD[j][t] = 0.f;
#pragma unroll
        for (int s = 0; s < 8; s++) {
            unsigned qa[8];
            qa[0] = __float_as_uint(Qs[(rw + g) * FQS + 8 * s + tig]);
            qa[1] = __float_as_uint(Qs[(rw + g + 8) * FQS + 8 * s + tig]);
            qa[2] = __float_as_uint(Qs[(rw + g) * FQS + 8 * s + tig + 4]);
            qa[3] = __float_as_uint(Qs[(rw + g + 8) * FQS + 8 * s + tig + 4]);
            qa[4] = __float_as_uint(Qs[(rw + g + 16) * FQS + 8 * s + tig]);
            qa[5] = __float_as_uint(Qs[(rw + g + 24) * FQS + 8 * s + tig]);
            qa[6] = __float_as_uint(Qs[(rw + g + 16) * FQS + 8 * s + tig + 4]);
            qa[7] = __float_as_uint(Qs[(rw + g + 24) * FQS + 8 * s + tig + 4]);
#pragma unroll
            for (int j = 0; j < 8; j++) {
                unsigned b0 = __float_as_uint(Kb[(8 * j + g) * FQS + 8 * s + tig]);
                unsigned b1 = __float_as_uint(Kb[(8 * j + g) * FQS + 8 * s + tig + 4]);
                mma8(&sD[j][0], qa, b0, b1);
                mma8(&sD[j][4], qa + 4, b0, b1);
            }
        }

        unsigned long long m64[4];
#pragma unroll
        for (int t = 0; t < 4; t++)
            m64[t] = pmask[(size_t)(q0 + rw + g + 8 * t) * NKT32 + kt];

        // no-max softmax: |score*log2e| <= ~12 -> ex2 safe; P fed raw (mma truncates,
        // lsum sums the same raw values so the truncation bias mostly cancels)
#pragma unroll
        for (int j = 0; j < 8; j++) {
#pragma unroll
            for (int t = 0; t < 4; t++) {
                unsigned pair = (unsigned)(m64[t] >> (8 * j + 2 * tig)) & 3u;
                float p0 = (pair & 1u) ? ex2(sD[j][2 * t] * scale2) : 0.f;
                float p1 = (pair & 2u) ? ex2(sD[j][2 * t + 1] * scale2) : 0.f;
                lsum[t] += p0 + p1;
                *(float2*)&Ps[(rw + g + 8 * t) * FQS + 8 * j + 2 * tig] = make_float2(p0, p1);
            }
        }
        __syncwarp();   // Ps rows rw..rw+31 produced & consumed within same warp

        // ctx += P @ V
#pragma unroll
        for (int s = 0; s < 8; s++) {
            unsigned pa[8];
            pa[0] = __float_as_uint(Ps[(rw + g) * FQS + 8 * s + tig]);
            pa[1] = __float_as_uint(Ps[(rw + g + 8) * FQS + 8 * s + tig]);
            pa[2] = __float_as_uint(Ps[(rw + g) * FQS + 8 * s + tig + 4]);
            pa[3] = __float_as_uint(Ps[(rw + g + 8) * FQS + 8 * s + tig + 4]);
            pa[4] = __float_as_uint(Ps[(rw + g + 16) * FQS + 8 * s + tig]);
            pa[5] = __float_as_uint(Ps[(rw + g + 24) * FQS + 8 * s + tig]);
            pa[6] = __float_as_uint(Ps[(rw + g + 16) * FQS + 8 * s + tig + 4]);
            pa[7] = __float_as_uint(Ps[(rw + g + 24) * FQS + 8 * s + tig + 4]);
#pragma unroll
            for (int j = 0; j < 8; j++) {
                unsigned b0 = __float_as_uint(Vb[(8 * s + tig) * FVS + 8 * j + g]);
                unsigned b1 = __float_as_uint(Vb[(8 * s + tig + 4) * FVS + 8 * j + g]);
                mma8(&acc[j][0], pa, b0, b1);
                mma8(&acc[j][4], pa + 4, b0, b1);
            }
        }
    }

#pragma unroll
    for (int t = 0; t < 4; t++) {
        lsum[t] += __shfl_xor_sync(0xffffffffu, lsum[t], 1);
        lsum[t] += __shfl_xor_sync(0xffffffffu, lsum[t], 2);
    }

    float inv[4];
#pragma unroll
    for (int t = 0; t < 4; t++) inv[t] = 1.0f / lsum[t];
#pragma unroll
    for (int j = 0; j < 8; j++) {
        int col = h * DK + 8 * j + 2 * tig;
#pragma unroll
        for (int t = 0; t < 4; t++) {
            *(float2*)&CTX[(size_t)(b * SEQ + q0 + rw + g + 8 * t) * DM + col] =
                make_float2(rna_tf32(acc[j][2 * t] * inv[t]),
                            rna_tf32(acc[j][2 * t + 1] * inv[t]));
        }
    }
}

// ---------------- in-place RMSNorm ----------------
__global__ void __launch_bounds__(256) rmsnorm_kernel(float* __restrict__ out,
                                                      const float* __restrict__ gamma) {
    int row = blockIdx.x;
    int tid = threadIdx.x;
    float4 x = *(const float4*)&out[(size_t)row * DM + (tid << 2)];
    float ss = x.x * x.x + x.y * x.y + x.z * x.z + x.w * x.w;
    __shared__ float red[8];
#pragma unroll
    for (int o = 16; o > 0; o >>= 1) ss += __shfl_xor_sync(0xffffffffu, ss, o);
    if ((tid & 31) == 0) red[tid >> 5] = ss;
    __syncthreads();
    if (tid < 8) {
        float sv = red[tid];
#pragma unroll
        for (int o = 4; o > 0; o >>= 1) sv += __shfl_xor_sync(0xffu, sv, o);
        if (tid == 0) red[0] = sv;
    }
    __syncthreads();
    float rms = rsqrtf(red[0] * (1.0f / (float)DM) + 1e-6f);
    float4 g = *(const float4*)&gamma[tid << 2];
    x.x *= rms * g.x; x.y *= rms * g.y; x.z *= rms * g.z; x.w *= rms * g.w;
    *(float4*)&out[(size_t)row * DM + (tid << 2)] = x;
}

// ---------------- launch ----------------
extern "C" void kernel_launch(void* const* d_in, const int* in_sizes, int n_in,
                              void* d_out, int out_size) {
    (void)in_sizes; (void)n_in; (void)out_size;
    const float* Q    = (const float*)d_in[0];
    const float* K    = (const float*)d_in[1];
    const float* V    = (const float*)d_in[2];
    const int*   mask = (const int*)d_in[3];
    const float* wq   = (const float*)d_in[4];
    const float* bq   = (const float*)d_in[5];
    const float* wk   = (const float*)d_in[6];
    const float* bk   = (const float*)d_in[7];
    const float* wv   = (const float*)d_in[8];
    const float* bv   = (const float*)d_in[9];
    const float* wo   = (const float*)d_in[10];
    const float* bo   = (const float*)d_in[11];
    const float* wnq  = (const float*)d_in[12];
    const float* bnq  = (const float*)d_in[13];
    const float* wnk  = (const float*)d_in[14];
    const float* bnk  = (const float*)d_in[15];
    const float* temp = (const float*)d_in[16];
    const float* gamma= (const float*)d_in[17];
    float* out = (float*)d_out;

    float *WQP, *WKP, *WVR, *WOR, *BQP, *BKP, *QR, *KR, *VR, *QFp, *KFp, *VPp, *CTXp;
    unsigned long long* PM;
    cudaGetSymbolAddress((void**)&WQP, g_WQP);
    cudaGetSymbolAddress((void**)&WKP, g_WKP);
    cudaGetSymbolAddress((void**)&WVR, g_WVR);
    cudaGetSymbolAddress((void**)&WOR, g_WOR);
    cudaGetSymbolAddress((void**)&BQP, g_BQP);
    cudaGetSymbolAddress((void**)&BKP, g_BKP);
    cudaGetSymbolAddress((void**)&QR, g_QR);
    cudaGetSymbolAddress((void**)&KR, g_KR);
    cudaGetSymbolAddress((void**)&VR, g_VR);
    cudaGetSymbolAddress((void**)&QFp, g_QF);
    cudaGetSymbolAddress((void**)&KFp, g_KF);
    cudaGetSymbolAddress((void**)&VPp, g_VP);
    cudaGetSymbolAddress((void**)&CTXp, g_CTX);
    cudaGetSymbolAddress((void**)&PM, g_PM);

    cudaFuncSetAttribute(gemm_tc, cudaFuncAttributeMaxDynamicSharedMemorySize, GEMM_SMEM);
    cudaFuncSetAttribute(gemm_qkv, cudaFuncAttributeMaxDynamicSharedMemorySize, GEMM_SMEM);
    cudaFuncSetAttribute(flash_tc, cudaFuncAttributeMaxDynamicSharedMemorySize, FLASH_SMEM);

    // prepasses (z-batched)
    dim3 rc3(512, 1, 3);
    round_copy3<<<rc3, 256>>>(Q, QR, K, KR, V, VR, NTOK * DM / 4);
    dim3 rc2(128, 1, 3);   // z=2 unused slot points at wv again (harmless rewrite)
    round_copy3<<<dim3(128, 1, 2), 256>>>(wv, WVR, wo, WOR, wo, WOR, DM * DM / 4);
    pack_mask<<<(SEQ * NKT32 + 255) / 256, 256>>>(mask, PM);
    fold_weights<<<DM * DM / 256, 256>>>(wq, bq, wnq, bnq, WQP, BQP);
    fold_weights<<<DM * DM / 256, 256>>>(wk, bk, wnk, bnk, WKP, BKP);

    // QKV projections in one launch
    dim3 ggrid(DM / GBN, NTOK / GBM, 3);
    gemm_qkv<<<ggrid, 256, GEMM_SMEM>>>(QR, WQP, BQP, QFp,
                                        KR, WKP, BKP, KFp,
                                        VR, WVR, bv, VPp);

    dim3 agrid(SEQ / FBM, NH, 2);
    flash_tc<<<agrid, 256, FLASH_SMEM>>>(QFp, KFp, VPp, PM, temp, CTXp);

    dim3 ogrid(DM / GBN, NTOK / GBM);
    gemm_tc<<<ogrid, 256, GEMM_SMEM>>>(CTXp, WOR, bo, out, 0);
    rmsnorm_kernel<<<NTOK, 256>>>(out, gamma);
}

// round 12
// speedup vs baseline: 1.2183x; 1.0021x over previous
#include <cuda_runtime.h>
#include <math.h>

#define DM 1024
#define NH 16
#define DK 64
#define SEQ 2048
#define NTOK 4096   // B * SEQ
#define NKT32 (SEQ / 64)   // packed-mask words per row

// ---------------- scratch (device globals) ----------------
__device__ float g_WQP[DM * DM];
__device__ float g_WKP[DM * DM];
__device__ float g_WVR[DM * DM];
__device__ float g_WOR[DM * DM];
__device__ float g_BQP[DM];
__device__ float g_BKP[DM];
__device__ float g_QR[NTOK * DM];
__device__ float g_KR[NTOK * DM];
__device__ float g_VR[NTOK * DM];
__device__ float g_QF[NTOK * DM];
__device__ float g_KF[NTOK * DM];
__device__ float g_VP[NTOK * DM];
__device__ float g_CTX[NTOK * DM];
__device__ unsigned long long g_PM[SEQ * NKT32];

// ---------------- helpers ----------------
__device__ __forceinline__ float rna_tf32(float x) {
    unsigned u;
    asm("cvt.rna.tf32.f32 %0, %1;" : "=r"(u) : "f"(x));
    return __uint_as_float(u);
}
__device__ __forceinline__ float ex2(float x) {
    float r;
    asm("ex2.approx.f32 %0, %1;" : "=f"(r) : "f"(x));
    return r;
}

__device__ __forceinline__ void mma8(float* c, const unsigned* a, unsigned b0, unsigned b1) {
    asm volatile(
        "mma.sync.aligned.m16n8k8.row.col.f32.tf32.tf32.f32 "
        "{%0,%1,%2,%3},{%4,%5,%6,%7},{%8,%9},{%0,%1,%2,%3};"
        : "+f"(c[0]), "+f"(c[1]), "+f"(c[2]), "+f"(c[3])
        : "r"(a[0]), "r"(a[1]), "r"(a[2]), "r"(a[3]), "r"(b0), "r"(b1));
}

__device__ __forceinline__ void cp16(const void* dst_smem, const void* src) {
    unsigned s = (unsigned)__cvta_generic_to_shared(dst_smem);
    asm volatile("cp.async.cg.shared.global [%0], [%1], 16;\n" :: "r"(s), "l"(src));
}
__device__ __forceinline__ void cp_commit() {
    asm volatile("cp.async.commit_group;\n");
}
template <int N>
__device__ __forceinline__ void cp_wait() {
    asm volatile("cp.async.wait_group %0;\n" :: "n"(N));
}

// ---------------- prepass: tf32-round tensors, z-batched ----------------
__global__ void round_copy3(const float* __restrict__ s0, float* __restrict__ d0,
                            const float* __restrict__ s1, float* __restrict__ d1,
                            const float* __restrict__ s2, float* __restrict__ d2, int n4) {
    const float* src = blockIdx.z == 0 ? s0 : (blockIdx.z == 1 ? s1 : s2);
    float* dst = blockIdx.z == 0 ? d0 : (blockIdx.z == 1 ? d1 : d2);
    int stride = gridDim.x * blockDim.x;
    for (int i = blockIdx.x * blockDim.x + threadIdx.x; i < n4; i += stride) {
        float4 v = *(const float4*)&src[(size_t)i << 2];
        v.x = rna_tf32(v.x); v.y = rna_tf32(v.y);
        v.z = rna_tf32(v.z); v.w = rna_tf32(v.w);
        *(float4*)&dst[(size_t)i << 2] = v;
    }
}

// ---------------- prepass: pack mask bits ----------------
__global__ void pack_mask(const int* __restrict__ mask, unsigned long long* __restrict__ pm) {
    int idx = blockIdx.x * blockDim.x + threadIdx.x;
    if (idx >= SEQ * NKT32) return;
    int q = idx / NKT32, kt = idx % NKT32;
    const int* src = mask + (size_t)q * SEQ + kt * 64;
    unsigned long long bits = 0ull;
#pragma unroll
    for (int i = 0; i < 16; i++) {
        int4 v = *(const int4*)(src + 4 * i);
        unsigned long long b = (unsigned long long)((v.x ? 1u : 0u) | (v.y ? 2u : 0u) |
                                                    (v.z ? 4u : 0u) | (v.w ? 8u : 0u));
        bits |= b << (4 * i);
    }
    pm[idx] = bits;
}

// ---------------- fold per-head feature-map weights (smem wn, z-batched) ------------
__global__ void __launch_bounds__(256) fold2(
    const float* __restrict__ wq, const float* __restrict__ bq,
    const float* __restrict__ wnq, const float* __restrict__ bnq,
    float* __restrict__ WQP, float* __restrict__ BQP,
    const float* __restrict__ wk, const float* __restrict__ bk,
    const float* __restrict__ wnk, const float* __restrict__ bnk,
    float* __restrict__ WKP, float* __restrict__ BKP) {
    const float* w  = blockIdx.z ? wk : wq;
    const float* b  = blockIdx.z ? bk : bq;
    const float* wn = blockIdx.z ? wnk : wnq;
    const float* bn = blockIdx.z ? bnk : bnq;
    float* wout = blockIdx.z ? WKP : WQP;
    float* bout = blockIdx.z ? BKP : BQP;
    __shared__ float wns[64 * 64];
    int tid = threadIdx.x;
    for (int i = tid; i < 4096; i += 256) wns[i] = wn[i];
    __syncthreads();
    int idx = blockIdx.x * 256 + tid;
    int i = idx >> 10, j = idx & 1023;
    int h = j >> 6, jj = j & 63;
    const float4* wrow = (const float4*)(w + (size_t)i * DM + h * DK);
    float acc = 0.f;
#pragma unroll
    for (int d4 = 0; d4 < 16; d4++) {
        float4 wv = wrow[d4];
        acc += wv.x * wns[(4 * d4 + 0) * 64 + jj];
        acc += wv.y * wns[(4 * d4 + 1) * 64 + jj];
        acc += wv.z * wns[(4 * d4 + 2) * 64 + jj];
        acc += wv.w * wns[(4 * d4 + 3) * 64 + jj];
    }
    wout[idx] = rna_tf32(acc);
    if (i == 0) {
        float bb = bn[jj];
        for (int d = 0; d < DK; d++) bb += b[h * DK + d] * wns[d * 64 + jj];
        bout[j] = bb;
    }
}

// ---------------- tf32 TC GEMM, 3-stage cp.async pipeline ----------------
#define GBM 128
#define GBN 256
#define GBK 32
#define GAS 36
#define GBS 264
#define GST 3
#define GEMM_SMEM (GST * (GBM * GAS + GBK * GBS) * 4)

__device__ __forceinline__ void gemm_body(
    const float* __restrict__ A, const float* __restrict__ W,
    const float* __restrict__ bias, float* __restrict__ C, int act,
    float* sg, int bm, int bn) {
    float* As = sg;
    float* Bs = sg + GST * GBM * GAS;

    int tid = threadIdx.x;
    int warp = tid >> 5, lane = tid & 31;
    int g = lane >> 2, tig = lane & 3;
    int wm = warp >> 2, wn = warp & 3;

    int ar[4], ak[4], bkr[8], bn4[8];
#pragma unroll
    for (int i = 0; i < 4; i++) {
        int idx = tid + 256 * i;
        ar[i] = idx >> 3;  ak[i] = (idx & 7) << 2;
    }
#pragma unroll
    for (int i = 0; i < 8; i++) {
        int idx = tid + 256 * i;
        bkr[i] = idx >> 6;  bn4[i] = (idx & 63) << 2;
    }

    float acc[4][8][4];
#pragma unroll
    for (int m = 0; m < 4; m++)
#pragma unroll
        for (int j = 0; j < 8; j++)
#pragma unroll
            for (int t = 0; t < 4; t++) acc[m][j][t] = 0.f;

#define GFILL(CK, BUF)                                                                  \
    do {                                                                                \
        int k0_ = (CK) * GBK;                                                           \
        float* An_ = As + (BUF) * GBM * GAS;                                            \
        float* Bn_ = Bs + (BUF) * GBK * GBS;                                            \
        _Pragma("unroll")                                                               \
        for (int i = 0; i < 4; i++)                                                     \
            cp16(&An_[ar[i] * GAS + ak[i]], &A[(size_t)(bm + ar[i]) * DM + k0_ + ak[i]]); \
        _Pragma("unroll")                                                               \
        for (int i = 0; i < 8; i++)                                                     \
            cp16(&Bn_[bkr[i] * GBS + bn4[i]], &W[(size_t)(k0_ + bkr[i]) * DM + bn + bn4[i]]); \
    } while (0)

    GFILL(0, 0); cp_commit();
    GFILL(1, 1); cp_commit();

    const int NK = DM / GBK;
    for (int kt = 0; kt < NK; kt++) {
        int buf = kt % GST;
        __syncthreads();
        if (kt + 2 < NK) {
            GFILL(kt + 2, (kt + 2) % GST);
            cp_commit();
            cp_wait<2>();
        } else if (kt + 1 < NK) {
            cp_wait<1>();
        } else {
            cp_wait<0>();
        }
        __syncthreads();

        float* Ab = As + buf * GBM * GAS;
        float* Bb = Bs + buf * GBK * GBS;
#pragma unroll
        for (int s = 0; s < 4; s++) {
            unsigned a[4][4], bb[8][2];
#pragma unroll
            for (int m = 0; m < 4; m++) {
                int m0 = wm * 64 + m * 16;
                a[m][0] = __float_as_uint(Ab[(m0 + g) * GAS + 8 * s + tig]);
                a[m][1] = __float_as_uint(Ab[(m0 + g + 8) * GAS + 8 * s + tig]);
                a[m][2] = __float_as_uint(Ab[(m0 + g) * GAS + 8 * s + tig + 4]);
                a[m][3] = __float_as_uint(Ab[(m0 + g + 8) * GAS + 8 * s + tig + 4]);
            }
#pragma unroll
            for (int j = 0; j < 8; j++) {
                int n0 = wn * 64 + j * 8;
                bb[j][0] = __float_as_uint(Bb[(8 * s + tig) * GBS + n0 + g]);
                bb[j][1] = __float_as_uint(Bb[(8 * s + tig + 4) * GBS + n0 + g]);
            }
#pragma unroll
            for (int m = 0; m < 4; m++)
#pragma unroll
                for (int j = 0; j < 8; j++)
                    mma8(acc[m][j], a[m], bb[j][0], bb[j][1]);
        }
    }
#undef GFILL

#pragma unroll
    for (int m = 0; m < 4; m++) {
        int row0 = bm + wm * 64 + m * 16 + g;
#pragma unroll
        for (int j = 0; j < 8; j++) {
            int col = bn + wn * 64 + j * 8 + 2 * tig;
            float b0 = bias[col], b1 = bias[col + 1];
            float v0 = acc[m][j][0] + b0, v1 = acc[m][j][1] + b1;
            float v2 = acc[m][j][2] + b0, v3 = acc[m][j][3] + b1;
            if (act == 1) {
                v0 = rna_tf32(tanhf(v0)); v1 = rna_tf32(tanhf(v1));
                v2 = rna_tf32(tanhf(v2)); v3 = rna_tf32(tanhf(v3));
            } else if (act == 2) {
                v0 = rna_tf32(v0); v1 = rna_tf32(v1);
                v2 = rna_tf32(v2); v3 = rna_tf32(v3);
            }
            *(float2*)&C[(size_t)row0 * DM + col] = make_float2(v0, v1);
            *(float2*)&C[(size_t)(row0 + 8) * DM + col] = make_float2(v2, v3);
        }
    }
}

// batched QKV projection (z selects operand set); act: Q=1 K=1 V=2
__global__ void __launch_bounds__(256) gemm_qkv(
    const float* __restrict__ A0, const float* __restrict__ W0, const float* __restrict__ b0, float* __restrict__ C0,
    const float* __restrict__ A1, const float* __restrict__ W1, const float* __restrict__ b1, float* __restrict__ C1,
    const float* __restrict__ A2, const float* __restrict__ W2, const float* __restrict__ b2, float* __restrict__ C2) {
    extern __shared__ __align__(16) float sg[];
    int z = blockIdx.z;
    const float* A = z == 0 ? A0 : (z == 1 ? A1 : A2);
    const float* W = z == 0 ? W0 : (z == 1 ? W1 : W2);
    const float* bias = z == 0 ? b0 : (z == 1 ? b1 : b2);
    float* C = z == 0 ? C0 : (z == 1 ? C1 : C2);
    int act = z == 2 ? 2 : 1;
    gemm_body(A, W, bias, C, act, sg, blockIdx.y * GBM, blockIdx.x * GBN);
}

__global__ void __launch_bounds__(256) gemm_tc(
    const float* __restrict__ A, const float* __restrict__ W,
    const float* __restrict__ bias, float* __restrict__ C, int act) {
    extern __shared__ __align__(16) float sg[];
    gemm_body(A, W, bias, C, act, sg, blockIdx.y * GBM, blockIdx.x * GBN);
}

// ---------------- flash attention: no-max softmax, packed mask, tf32 throughout -----
#define FQS 68
#define FVS 72
#define FBM 256
#define FLASH_SMEM ((FBM * FQS * 2 + 2 * 64 * FQS + 2 * 64 * FVS) * 4)

__global__ void __launch_bounds__(256) flash_tc(
    const float* __restrict__ QF, const float* __restrict__ KF,
    const float* __restrict__ V, const unsigned long long* __restrict__ pmask,
    const float* __restrict__ temp, float* __restrict__ CTX) {
    extern __shared__ __align__(16) float sm[];
    float* Qs = sm;                          // 256 x FQS
    float* Ps = sm + FBM * FQS;              // 256 x FQS
    float* Ks = Ps + FBM * FQS;              // 2 x 64 x FQS
    float* Vs = Ks + 2 * 64 * FQS;           // 2 x 64 x FVS

    int tid = threadIdx.x;
    int warp = tid >> 5, lane = tid & 31;
    int g = lane >> 2, tig = lane & 3;
    int q0 = blockIdx.x * FBM, h = blockIdx.y, b = blockIdx.z;
    int rw = warp * 32;

#pragma unroll
    for (int i = 0; i < 16; i++) {
        int idx = tid + 256 * i;
        int r = idx >> 4, d4 = (idx & 15) << 2;
        *(float4*)&Qs[r * FQS + d4] =
            *(const float4*)&QF[(size_t)(b * SEQ + q0 + r) * DM + h * DK + d4];
    }

    int lr[4], ld4[4];
#pragma unroll
    for (int i = 0; i < 4; i++) {
        int idx = tid + 256 * i;
        lr[i] = idx >> 4;  ld4[i] = (idx & 15) << 2;
    }

    float scale2 = (0.125f / temp[h]) * 1.44269504088896f;
    float lsum[4] = {0.f, 0.f, 0.f, 0.f};
    float acc[8][8];
#pragma unroll
    for (int j = 0; j < 8; j++)
#pragma unroll
        for (int t = 0; t < 8; t++) acc[j][t] = 0.f;

#pragma unroll
    for (int i = 0; i < 4; i++) {
        size_t src = (size_t)(b * SEQ + lr[i]) * DM + h * DK + ld4[i];
        cp16(&Ks[lr[i] * FQS + ld4[i]], &KF[src]);
        cp16(&Vs[lr[i] * FVS + ld4[i]], &V[src]);
    }
    cp_commit();
    __syncthreads();

    const int NKT = SEQ / 64;
    for (int kt = 0; kt < NKT; kt++) {
        int buf = kt & 1;
        float* Kb = Ks + buf * 64 * FQS;
        float* Vb = Vs + buf * 64 * FVS;
        __syncthreads();
        if (kt + 1 < NKT) {
            float* Kn = Ks + (buf ^ 1) * 64 * FQS;
            float* Vn = Vs + (buf ^ 1) * 64 * FVS;
#pragma unroll
            for (int i = 0; i < 4; i++) {
                size_t src = (size_t)(b * SEQ + (kt + 1) * 64 + lr[i]) * DM + h * DK + ld4[i];
                cp16(&Kn[lr[i] * FQS + ld4[i]], &KF[src]);
                cp16(&Vn[lr[i] * FVS + ld4[i]], &V[src]);
            }
            cp_commit();
            cp_wait<1>();
        } else {
            cp_wait<0>();
        }
        __syncthreads();

        // S = Qf @ Kf^T  (tf32 k8, 32 q-rows per warp)
        float sD[8][8];
#pragma unroll
        for (int j = 0; j < 8; j++)
#pragma unroll
            for (int t = 0; t < 8; t++) sD[j][t] = 0.f;
#pragma unroll
        for (int s = 0; s < 8; s++) {
            unsigned qa[8];
            qa[0] = __float_as_uint(Qs[(rw + g) * FQS + 8 * s + tig]);
            qa[1] = __float_as_uint(Qs[(rw + g + 8) * FQS + 8 * s + tig]);
            qa[2] = __float_as_uint(Qs[(rw + g) * FQS + 8 * s + tig + 4]);
            qa[3] = __float_as_uint(Qs[(rw + g + 8) * FQS + 8 * s + tig + 4]);
            qa[4] = __float_as_uint(Qs[(rw + g + 16) * FQS + 8 * s + tig]);
            qa[5] = __float_as_uint(Qs[(rw + g + 24) * FQS + 8 * s + tig]);
            qa[6] = __float_as_uint(Qs[(rw + g + 16) * FQS + 8 * s + tig + 4]);
            qa[7] = __float_as_uint(Qs[(rw + g + 24) * FQS + 8 * s + tig + 4]);
#pragma unroll
            for (int j = 0; j < 8; j++) {
                unsigned b0 = __float_as_uint(Kb[(8 * j + g) * FQS + 8 * s + tig]);
                unsigned b1 = __float_as_uint(Kb[(8 * j + g) * FQS + 8 * s + tig + 4]);
                mma8(&sD[j][0], qa, b0, b1);
                mma8(&sD[j][4], qa + 4, b0, b1);
            }
        }

        unsigned long long m64[4];
#pragma unroll
        for (int t = 0; t < 4; t++)
            m64[t] = pmask[(size_t)(q0 + rw + g + 8 * t) * NKT32 + kt];

        // no-max softmax (|score*log2e| <= ~12 -> ex2 safe); P raw fp32 into smem
#pragma unroll
        for (int j = 0; j < 8; j++) {
#pragma unroll
            for (int t = 0; t < 4; t++) {
                unsigned pair = (unsigned)(m64[t] >> (8 * j + 2 * tig)) & 3u;
                float p0 = (pair & 1u) ? ex2(sD[j][2 * t] * scale2) : 0.f;
                float p1 = (pair & 2u) ? ex2(sD[j][2 * t + 1] * scale2) : 0.f;
                lsum[t] += p0 + p1;
                *(float2*)&Ps[(rw + g + 8 * t) * FQS + 8 * j + 2 * tig] = make_float2(p0, p1);
            }
        }
        __syncwarp();   // Ps rows rw..rw+31 produced & consumed within same warp

        // ctx += P @ V  (tf32 k8)
#pragma unroll
        for (int s = 0; s < 8; s++) {
            unsigned pa[8];
            pa[0] = __float_as_uint(Ps[(rw + g) * FQS + 8 * s + tig]);
            pa[1] = __float_as_uint(Ps[(rw + g + 8) * FQS + 8 * s + tig]);
            pa[2] = __float_as_uint(Ps[(rw + g) * FQS + 8 * s + tig + 4]);
            pa[3] = __float_as_uint(Ps[(rw + g + 8) * FQS + 8 * s + tig + 4]);
            pa[4] = __float_as_uint(Ps[(rw + g + 16) * FQS + 8 * s + tig]);
            pa[5] = __float_as_uint(Ps[(rw + g + 24) * FQS + 8 * s + tig]);
            pa[6] = __float_as_uint(Ps[(rw + g + 16) * FQS + 8 * s + tig + 4]);
            pa[7] = __float_as_uint(Ps[(rw + g + 24) * FQS + 8 * s + tig + 4]);
#pragma unroll
            for (int j = 0; j < 8; j++) {
                unsigned b0 = __float_as_uint(Vb[(8 * s + tig) * FVS + 8 * j + g]);
                unsigned b1 = __float_as_uint(Vb[(8 * s + tig + 4) * FVS + 8 * j + g]);
                mma8(&acc[j][0], pa, b0, b1);
                mma8(&acc[j][4], pa + 4, b0, b1);
            }
        }
    }

#pragma unroll
    for (int t = 0; t < 4; t++) {
        lsum[t] += __shfl_xor_sync(0xffffffffu, lsum[t], 1);
        lsum[t] += __shfl_xor_sync(0xffffffffu, lsum[t], 2);
    }
    float inv[4];
#pragma unroll
    for (int t = 0; t < 4; t++) inv[t] = 1.0f / lsum[t];
#pragma unroll
    for (int j = 0; j < 8; j++) {
        int col = h * DK + 8 * j + 2 * tig;
#pragma unroll
        for (int t = 0; t < 4; t++) {
            *(float2*)&CTX[(size_t)(b * SEQ + q0 + rw + g + 8 * t) * DM + col] =
                make_float2(rna_tf32(acc[j][2 * t] * inv[t]),
                            rna_tf32(acc[j][2 * t + 1] * inv[t]));
        }
    }
}

// ---------------- in-place RMSNorm ----------------
__global__ void __launch_bounds__(256) rmsnorm_kernel(float* __restrict__ out,
                                                      const float* __restrict__ gamma) {
    int row = blockIdx.x;
    int tid = threadIdx.x;
    float4 x = *(const float4*)&out[(size_t)row * DM + (tid << 2)];
    float ss = x.x * x.x + x.y * x.y + x.z * x.z + x.w * x.w;
    __shared__ float red[8];
#pragma unroll
    for (int o = 16; o > 0; o >>= 1) ss += __shfl_xor_sync(0xffffffffu, ss, o);
    if ((tid & 31) == 0) red[tid >> 5] = ss;
    __syncthreads();
    if (tid < 8) {
        float sv = red[tid];
#pragma unroll
        for (int o = 4; o > 0; o >>= 1) sv += __shfl_xor_sync(0xffu, sv, o);
        if (tid == 0) red[0] = sv;
    }
    __syncthreads();
    float rms = rsqrtf(red[0] * (1.0f / (float)DM) + 1e-6f);
    float4 g = *(const float4*)&gamma[tid << 2];
    x.x *= rms * g.x; x.y *= rms * g.y; x.z *= rms * g.z; x.w *= rms * g.w;
    *(float4*)&out[(size_t)row * DM + (tid << 2)] = x;
}

// ---------------- launch ----------------
extern "C" void kernel_launch(void* const* d_in, const int* in_sizes, int n_in,
                              void* d_out, int out_size) {
    (void)in_sizes; (void)n_in; (void)out_size;
    const float* Q    = (const float*)d_in[0];
    const float* K    = (const float*)d_in[1];
    const float* V    = (const float*)d_in[2];
    const int*   mask = (const int*)d_in[3];
    const float* wq   = (const float*)d_in[4];
    const float* bq   = (const float*)d_in[5];
    const float* wk   = (const float*)d_in[6];
    const float* bk   = (const float*)d_in[7];
    const float* wv   = (const float*)d_in[8];
    const float* bv   = (const float*)d_in[9];
    const float* wo   = (const float*)d_in[10];
    const float* bo   = (const float*)d_in[11];
    const float* wnq  = (const float*)d_in[12];
    const float* bnq  = (const float*)d_in[13];
    const float* wnk  = (const float*)d_in[14];
    const float* bnk  = (const float*)d_in[15];
    const float* temp = (const float*)d_in[16];
    const float* gamma= (const float*)d_in[17];
    float* out = (float*)d_out;

    float *WQP, *WKP, *WVR, *WOR, *BQP, *BKP, *QR, *KR, *VR, *QFp, *KFp, *VPp, *CTXp;
    unsigned long long* PM;
    cudaGetSymbolAddress((void**)&WQP, g_WQP);
    cudaGetSymbolAddress((void**)&WKP, g_WKP);
    cudaGetSymbolAddress((void**)&WVR, g_WVR);
    cudaGetSymbolAddress((void**)&WOR, g_WOR);
    cudaGetSymbolAddress((void**)&BQP, g_BQP);
    cudaGetSymbolAddress((void**)&BKP, g_BKP);
    cudaGetSymbolAddress((void**)&QR, g_QR);
    cudaGetSymbolAddress((void**)&KR, g_KR);
    cudaGetSymbolAddress((void**)&VR, g_VR);
    cudaGetSymbolAddress((void**)&QFp, g_QF);
    cudaGetSymbolAddress((void**)&KFp, g_KF);
    cudaGetSymbolAddress((void**)&VPp, g_VP);
    cudaGetSymbolAddress((void**)&CTXp, g_CTX);
    cudaGetSymbolAddress((void**)&PM, g_PM);

    cudaFuncSetAttribute(gemm_tc, cudaFuncAttributeMaxDynamicSharedMemorySize, GEMM_SMEM);
    cudaFuncSetAttribute(gemm_qkv, cudaFuncAttributeMaxDynamicSharedMemorySize, GEMM_SMEM);
    cudaFuncSetAttribute(flash_tc, cudaFuncAttributeMaxDynamicSharedMemorySize, FLASH_SMEM);

    // prepasses
    round_copy3<<<dim3(512, 1, 3), 256>>>(Q, QR, K, KR, V, VR, NTOK * DM / 4);
    round_copy3<<<dim3(128, 1, 2), 256>>>(wv, WVR, wo, WOR, wo, WOR, DM * DM / 4);
    pack_mask<<<(SEQ * NKT32 + 255) / 256, 256>>>(mask, PM);
    fold2<<<dim3(DM * DM / 256, 1, 2), 256>>>(wq, bq, wnq, bnq, WQP, BQP,
                                              wk, bk, wnk, bnk, WKP, BKP);

    // QKV projections in one launch
    dim3 ggrid(DM / GBN, NTOK / GBM, 3);
    gemm_qkv<<<ggrid, 256, GEMM_SMEM>>>(QR, WQP, BQP, QFp,
                                        KR, WKP, BKP, KFp,
                                        VR, WVR, bv, VPp);

    dim3 agrid(SEQ / FBM, NH, 2);
    flash_tc<<<agrid, 256, FLASH_SMEM>>>(QFp, KFp, VPp, PM, temp, CTXp);

    dim3 ogrid(DM / GBN, NTOK / GBM);
    gemm_tc<<<ogrid, 256, GEMM_SMEM>>>(CTXp, WOR, bo, out, 0);
    rmsnorm_kernel<<<NTOK, 256>>>(out, gamma);
}

// round 13
// speedup vs baseline: 1.2876x; 1.0569x over previous
#include <cuda_runtime.h>
#include <math.h>

#define DM 1024
#define NH 16
#define DK 64
#define SEQ 2048
#define NTOK 4096   // B * SEQ
#define NKT32 (SEQ / 64)   // packed-mask words per row

// ---------------- scratch (device globals) ----------------
__device__ float g_WQP[DM * DM];
__device__ float g_WKP[DM * DM];
__device__ float g_WVR[DM * DM];
__device__ float g_WOR[DM * DM];
__device__ float g_BQP[DM];
__device__ float g_BKP[DM];
__device__ float g_QR[NTOK * DM];
__device__ float g_KR[NTOK * DM];
__device__ float g_VR[NTOK * DM];
__device__ float g_QF[NTOK * DM];
__device__ float g_KF[NTOK * DM];
__device__ float g_VP[NTOK * DM];
__device__ float g_CTX[NTOK * DM];
__device__ unsigned long long g_PM[SEQ * NKT32];

// ---------------- helpers ----------------
__device__ __forceinline__ float rna_tf32(float x) {
    unsigned u;
    asm("cvt.rna.tf32.f32 %0, %1;" : "=r"(u) : "f"(x));
    return __uint_as_float(u);
}
__device__ __forceinline__ float ex2(float x) {
    float r;
    asm("ex2.approx.f32 %0, %1;" : "=f"(r) : "f"(x));
    return r;
}

__device__ __forceinline__ void mma8(float* c, const unsigned* a, unsigned b0, unsigned b1) {
    asm volatile(
        "mma.sync.aligned.m16n8k8.row.col.f32.tf32.tf32.f32 "
        "{%0,%1,%2,%3},{%4,%5,%6,%7},{%8,%9},{%0,%1,%2,%3};"
        : "+f"(c[0]), "+f"(c[1]), "+f"(c[2]), "+f"(c[3])
        : "r"(a[0]), "r"(a[1]), "r"(a[2]), "r"(a[3]), "r"(b0), "r"(b1));
}

__device__ __forceinline__ void cp16(const void* dst_smem, const void* src) {
    unsigned s = (unsigned)__cvta_generic_to_shared(dst_smem);
    asm volatile("cp.async.cg.shared.global [%0], [%1], 16;\n" :: "r"(s), "l"(src));
}
__device__ __forceinline__ void cp_commit() {
    asm volatile("cp.async.commit_group;\n");
}
template <int N>
__device__ __forceinline__ void cp_wait() {
    asm volatile("cp.async.wait_group %0;\n" :: "n"(N));
}

// ---------------- prepass: tf32-round tensors, z-batched ----------------
__global__ void round_copy3(const float* __restrict__ s0, float* __restrict__ d0,
                            const float* __restrict__ s1, float* __restrict__ d1,
                            const float* __restrict__ s2, float* __restrict__ d2, int n4) {
    const float* src = blockIdx.z == 0 ? s0 : (blockIdx.z == 1 ? s1 : s2);
    float* dst = blockIdx.z == 0 ? d0 : (blockIdx.z == 1 ? d1 : d2);
    int stride = gridDim.x * blockDim.x;
    for (int i = blockIdx.x * blockDim.x + threadIdx.x; i < n4; i += stride) {
        float4 v = *(const float4*)&src[(size_t)i << 2];
        v.x = rna_tf32(v.x); v.y = rna_tf32(v.y);
        v.z = rna_tf32(v.z); v.w = rna_tf32(v.w);
        *(float4*)&dst[(size_t)i << 2] = v;
    }
}

// ---------------- prepass: pack mask bits ----------------
__global__ void pack_mask(const int* __restrict__ mask, unsigned long long* __restrict__ pm) {
    int idx = blockIdx.x * blockDim.x + threadIdx.x;
    if (idx >= SEQ * NKT32) return;
    int q = idx / NKT32, kt = idx % NKT32;
    const int* src = mask + (size_t)q * SEQ + kt * 64;
    unsigned long long bits = 0ull;
#pragma unroll
    for (int i = 0; i < 16; i++) {
        int4 v = *(const int4*)(src + 4 * i);
        unsigned long long b = (unsigned long long)((v.x ? 1u : 0u) | (v.y ? 2u : 0u) |
                                                    (v.z ? 4u : 0u) | (v.w ? 8u : 0u));
        bits |= b << (4 * i);
    }
    pm[idx] = bits;
}

// ---------------- fold v3: 4 outputs/thread, w-row + wn in smem --------------------
// block b (z in {0,1}) computes full output row i=b: 1024 outputs via 256 threads x4.
__global__ void __launch_bounds__(256) fold3(
    const float* __restrict__ wq, const float* __restrict__ bq,
    const float* __restrict__ wnq, const float* __restrict__ bnq,
    float* __restrict__ WQP, float* __restrict__ BQP,
    const float* __restrict__ wk, const float* __restrict__ bk,
    const float* __restrict__ wnk, const float* __restrict__ bnk,
    float* __restrict__ WKP, float* __restrict__ BKP) {
    const float* w  = blockIdx.z ? wk : wq;
    const float* b  = blockIdx.z ? bk : bq;
    const float* wn = blockIdx.z ? wnk : wnq;
    const float* bn = blockIdx.z ? bnk : bnq;
    float* wout = blockIdx.z ? WKP : WQP;
    float* bout = blockIdx.z ? BKP : BQP;
    __shared__ float wns[64 * 64];   // [k][jj]
    __shared__ float ws[DM];         // w row i
    int tid = threadIdx.x;
    int i = blockIdx.x;
    for (int t = tid; t < 4096; t += 256) wns[t] = wn[t];
    for (int t = tid; t < DM; t += 256) ws[t] = w[(size_t)i * DM + t];
    __syncthreads();

    int j4 = tid << 2;              // 4 consecutive outputs, same head
    int h = j4 >> 6, jj = j4 & 63;
    float a0 = 0.f, a1 = 0.f, a2 = 0.f, a3 = 0.f;
#pragma unroll 16
    for (int k = 0; k < DK; k++) {
        float wv = ws[h * DK + k];                      // broadcast LDS
        float4 n4 = *(const float4*)&wns[k * 64 + jj];  // LDS.128
        a0 += wv * n4.x; a1 += wv * n4.y;
        a2 += wv * n4.z; a3 += wv * n4.w;
    }
    float4 o;
    o.x = rna_tf32(a0); o.y = rna_tf32(a1);
    o.z = rna_tf32(a2); o.w = rna_tf32(a3);
    *(float4*)&wout[(size_t)i * DM + j4] = o;

    if (i == 0) {
        float b0 = bn[jj], b1 = bn[jj + 1], b2 = bn[jj + 2], b3 = bn[jj + 3];
        for (int d = 0; d < DK; d++) {
            float bv = b[h * DK + d];
            b0 += bv * wns[d * 64 + jj];
            b1 += bv * wns[d * 64 + jj + 1];
            b2 += bv * wns[d * 64 + jj + 2];
            b3 += bv * wns[d * 64 + jj + 3];
        }
        *(float4*)&bout[j4] = make_float4(b0, b1, b2, b3);
    }
}

// ---------------- tf32 TC GEMM, 4-stage cp.async pipeline ----------------
#define GBM 128
#define GBN 256
#define GBK 32
#define GAS 36
#define GBS 264
#define GST 4
#define GEMM_SMEM (GST * (GBM * GAS + GBK * GBS) * 4)

__device__ __forceinline__ void gemm_body(
    const float* __restrict__ A, const float* __restrict__ W,
    const float* __restrict__ bias, float* __restrict__ C, int act,
    float* sg, int bm, int bn) {
    float* As = sg;
    float* Bs = sg + GST * GBM * GAS;

    int tid = threadIdx.x;
    int warp = tid >> 5, lane = tid & 31;
    int g = lane >> 2, tig = lane & 3;
    int wm = warp >> 2, wn = warp & 3;

    int ar[4], ak[4], bkr[8], bn4[8];
#pragma unroll
    for (int i = 0; i < 4; i++) {
        int idx = tid + 256 * i;
        ar[i] = idx >> 3;  ak[i] = (idx & 7) << 2;
    }
#pragma unroll
    for (int i = 0; i < 8; i++) {
        int idx = tid + 256 * i;
        bkr[i] = idx >> 6;  bn4[i] = (idx & 63) << 2;
    }

    float acc[4][8][4];
#pragma unroll
    for (int m = 0; m < 4; m++)
#pragma unroll
        for (int j = 0; j < 8; j++)
#pragma unroll
            for (int t = 0; t < 4; t++) acc[m][j][t] = 0.f;

#define GFILL(CK, BUF)                                                                  \
    do {                                                                                \
        int k0_ = (CK) * GBK;                                                           \
        float* An_ = As + (BUF) * GBM * GAS;                                            \
        float* Bn_ = Bs + (BUF) * GBK * GBS;                                            \
        _Pragma("unroll")                                                               \
        for (int i = 0; i < 4; i++)                                                     \
            cp16(&An_[ar[i] * GAS + ak[i]], &A[(size_t)(bm + ar[i]) * DM + k0_ + ak[i]]); \
        _Pragma("unroll")                                                               \
        for (int i = 0; i < 8; i++)                                                     \
            cp16(&Bn_[bkr[i] * GBS + bn4[i]], &W[(size_t)(k0_ + bkr[i]) * DM + bn + bn4[i]]); \
    } while (0)

    GFILL(0, 0); cp_commit();
    GFILL(1, 1); cp_commit();
    GFILL(2, 2); cp_commit();

    const int NK = DM / GBK;
    for (int kt = 0; kt < NK; kt++) {
        int buf = kt % GST;
        __syncthreads();
        if (kt + 3 < NK) {
            GFILL(kt + 3, (kt + 3) % GST);
            cp_commit();
            cp_wait<3>();
        } else if (kt + 2 < NK) {
            cp_wait<2>();
        } else if (kt + 1 < NK) {
            cp_wait<1>();
        } else {
            cp_wait<0>();
        }
        __syncthreads();

        float* Ab = As + buf * GBM * GAS;
        float* Bb = Bs + buf * GBK * GBS;
#pragma unroll
        for (int s = 0; s < 4; s++) {
            unsigned a[4][4], bb[8][2];
#pragma unroll
            for (int m = 0; m < 4; m++) {
                int m0 = wm * 64 + m * 16;
                a[m][0] = __float_as_uint(Ab[(m0 + g) * GAS + 8 * s + tig]);
                a[m][1] = __float_as_uint(Ab[(m0 + g + 8) * GAS + 8 * s + tig]);
                a[m][2] = __float_as_uint(Ab[(m0 + g) * GAS + 8 * s + tig + 4]);
                a[m][3] = __float_as_uint(Ab[(m0 + g + 8) * GAS + 8 * s + tig + 4]);
            }
#pragma unroll
            for (int j = 0; j < 8; j++) {
                int n0 = wn * 64 + j * 8;
                bb[j][0] = __float_as_uint(Bb[(8 * s + tig) * GBS + n0 + g]);
                bb[j][1] = __float_as_uint(Bb[(8 * s + tig + 4) * GBS + n0 + g]);
            }
#pragma unroll
            for (int m = 0; m < 4; m++)
#pragma unroll
                for (int j = 0; j < 8; j++)
                    mma8(acc[m][j], a[m], bb[j][0], bb[j][1]);
        }
    }
#undef GFILL

#pragma unroll
    for (int m = 0; m < 4; m++) {
        int row0 = bm + wm * 64 + m * 16 + g;
#pragma unroll
        for (int j = 0; j < 8; j++) {
            int col = bn + wn * 64 + j * 8 + 2 * tig;
            float b0 = bias[col], b1 = bias[col + 1];
            float v0 = acc[m][j][0] + b0, v1 = acc[m][j][1] + b1;
            float v2 = acc[m][j][2] + b0, v3 = acc[m][j][3] + b1;
            if (act == 1) {
                v0 = rna_tf32(tanhf(v0)); v1 = rna_tf32(tanhf(v1));
                v2 = rna_tf32(tanhf(v2)); v3 = rna_tf32(tanhf(v3));
            } else if (act == 2) {
                v0 = rna_tf32(v0); v1 = rna_tf32(v1);
                v2 = rna_tf32(v2); v3 = rna_tf32(v3);
            }
            *(float2*)&C[(size_t)row0 * DM + col] = make_float2(v0, v1);
            *(float2*)&C[(size_t)(row0 + 8) * DM + col] = make_float2(v2, v3);
        }
    }
}

// batched QKV projection (z selects operand set); act: Q=1 K=1 V=2
__global__ void __launch_bounds__(256) gemm_qkv(
    const float* __restrict__ A0, const float* __restrict__ W0, const float* __restrict__ b0, float* __restrict__ C0,
    const float* __restrict__ A1, const float* __restrict__ W1, const float* __restrict__ b1, float* __restrict__ C1,
    const float* __restrict__ A2, const float* __restrict__ W2, const float* __restrict__ b2, float* __restrict__ C2) {
    extern __shared__ __align__(16) float sg[];
    int z = blockIdx.z;
    const float* A = z == 0 ? A0 : (z == 1 ? A1 : A2);
    const float* W = z == 0 ? W0 : (z == 1 ? W1 : W2);
    const float* bias = z == 0 ? b0 : (z == 1 ? b1 : b2);
    float* C = z == 0 ? C0 : (z == 1 ? C1 : C2);
    int act = z == 2 ? 2 : 1;
    gemm_body(A, W, bias, C, act, sg, blockIdx.y * GBM, blockIdx.x * GBN);
}

__global__ void __launch_bounds__(256) gemm_tc(
    const float* __restrict__ A, const float* __restrict__ W,
    const float* __restrict__ bias, float* __restrict__ C, int act) {
    extern __shared__ __align__(16) float sg[];
    gemm_body(A, W, bias, C, act, sg, blockIdx.y * GBM, blockIdx.x * GBN);
}

// ---------------- flash attention: no-max softmax, packed mask, tf32 throughout -----
#define FQS 68
#define FVS 72
#define FBM 256
#define FLASH_SMEM ((FBM * FQS * 2 + 2 * 64 * FQS + 2 * 64 * FVS) * 4)

__global__ void __launch_bounds__(256) flash_tc(
    const float* __restrict__ QF, const float* __restrict__ KF,
    const float* __restrict__ V, const unsigned long long* __restrict__ pmask,
    const float* __restrict__ temp, float* __restrict__ CTX) {
    extern __shared__ __align__(16) float sm[];
    float* Qs = sm;                          // 256 x FQS
    float* Ps = sm + FBM * FQS;              // 256 x FQS
    float* Ks = Ps + FBM * FQS;              // 2 x 64 x FQS
    float* Vs = Ks + 2 * 64 * FQS;           // 2 x 64 x FVS

    int tid = threadIdx.x;
    int warp = tid >> 5, lane = tid & 31;
    int g = lane >> 2, tig = lane & 3;
    int q0 = blockIdx.x * FBM, h = blockIdx.y, b = blockIdx.z;
    int rw = warp * 32;

#pragma unroll
    for (int i = 0; i < 16; i++) {
        int idx = tid + 256 * i;
        int r = idx >> 4, d4 = (idx & 15) << 2;
        *(float4*)&Qs[r * FQS + d4] =
            *(const float4*)&QF[(size_t)(b * SEQ + q0 + r) * DM + h * DK + d4];
    }

    int lr[4], ld4[4];
#pragma unroll
    for (int i = 0; i < 4; i++) {
        int idx = tid + 256 * i;
        lr[i] = idx >> 4;  ld4[i] = (idx & 15) << 2;
    }

    float scale2 = (0.125f / temp[h]) * 1.44269504088896f;
    float lsum[4] = {0.f, 0.f, 0.f, 0.f};
    float acc[8][8];
#pragma unroll
    for (int j = 0; j < 8; j++)
#pragma unroll
        for (int t = 0; t < 8; t++) acc[j][t] = 0.f;

#pragma unroll
    for (int i = 0; i < 4; i++) {
        size_t src = (size_t)(b * SEQ + lr[i]) * DM + h * DK + ld4[i];
        cp16(&Ks[lr[i] * FQS + ld4[i]], &KF[src]);
        cp16(&Vs[lr[i] * FVS + ld4[i]], &V[src]);
    }
    cp_commit();
    __syncthreads();

    const int NKT = SEQ / 64;
    for (int kt = 0; kt < NKT; kt++) {
        int buf = kt & 1;
        float* Kb = Ks + buf * 64 * FQS;
        float* Vb = Vs + buf * 64 * FVS;
        __syncthreads();
        if (kt + 1 < NKT) {
            float* Kn = Ks + (buf ^ 1) * 64 * FQS;
            float* Vn = Vs + (buf ^ 1) * 64 * FVS;
#pragma unroll
            for (int i = 0; i < 4; i++) {
                size_t src = (size_t)(b * SEQ + (kt + 1) * 64 + lr[i]) * DM + h * DK + ld4[i];
                cp16(&Kn[lr[i] * FQS + ld4[i]], &KF[src]);
                cp16(&Vn[lr[i] * FVS + ld4[i]], &V[src]);
            }
            cp_commit();
            cp_wait<1>();
        } else {
            cp_wait<0>();
        }
        __syncthreads();

        // mask prefetch FIRST: LDG retires under the mma stream below
        unsigned long long m64[4];
#pragma unroll
        for (int t = 0; t < 4; t++)
            m64[t] = pmask[(size_t)(q0 + rw + g + 8 * t) * NKT32 + kt];

        // S = Qf @ Kf^T  (tf32 k8, 32 q-rows per warp)
        float sD[8][8];
#pragma unroll
        for (int j = 0; j < 8; j++)
#pragma unroll
            for (int t = 0; t < 8; t++) sD[j][t] = 0.f;
#pragma unroll
        for (int s = 0; s < 8; s++) {
            unsigned qa[8];
            qa[0] = __float_as_uint(Qs[(rw + g) * FQS + 8 * s + tig]);
            qa[1] = __float_as_uint(Qs[(rw + g + 8) * FQS + 8 * s + tig]);
            qa[2] = __float_as_uint(Qs[(rw + g) * FQS + 8 * s + tig + 4]);
            qa[3] = __float_as_uint(Qs[(rw + g + 8) * FQS + 8 * s + tig + 4]);
            qa[4] = __float_as_uint(Qs[(rw + g + 16) * FQS + 8 * s + tig]);
            qa[5] = __float_as_uint(Qs[(rw + g + 24) * FQS + 8 * s + tig]);
            qa[6] = __float_as_uint(Qs[(rw + g + 16) * FQS + 8 * s + tig + 4]);
            qa[7] = __float_as_uint(Qs[(rw + g + 24) * FQS + 8 * s + tig + 4]);
#pragma unroll
            for (int j = 0; j < 8; j++) {
                unsigned b0 = __float_as_uint(Kb[(8 * j + g) * FQS + 8 * s + tig]);
                unsigned b1 = __float_as_uint(Kb[(8 * j + g) * FQS + 8 * s + tig + 4]);
                mma8(&sD[j][0], qa, b0, b1);
                mma8(&sD[j][4], qa + 4, b0, b1);
            }
        }

        // no-max softmax (|score*log2e| <= ~12 -> ex2 safe); P raw fp32 into smem
#pragma unroll
        for (int j = 0; j < 8; j++) {
#pragma unroll
            for (int t = 0; t < 4; t++) {
                unsigned pair = (unsigned)(m64[t] >> (8 * j + 2 * tig)) & 3u;
                float p0 = (pair & 1u) ? ex2(sD[j][2 * t] * scale2) : 0.f;
                float p1 = (pair & 2u) ? ex2(sD[j][2 * t + 1] * scale2) : 0.f;
                lsum[t] += p0 + p1;
                *(float2*)&Ps[(rw + g + 8 * t) * FQS + 8 * j + 2 * tig] = make_float2(p0, p1);
            }
        }
        __syncwarp();   // Ps rows rw..rw+31 produced & consumed within same warp

        // ctx += P @ V  (tf32 k8)
#pragma unroll
        for (int s = 0; s < 8; s++) {
            unsigned pa[8];
            pa[0] = __float_as_uint(Ps[(rw + g) * FQS + 8 * s + tig]);
            pa[1] = __float_as_uint(Ps[(rw + g + 8) * FQS + 8 * s + tig]);
            pa[2] = __float_as_uint(Ps[(rw + g) * FQS + 8 * s + tig + 4]);
            pa[3] = __float_as_uint(Ps[(rw + g + 8) * FQS + 8 * s + tig + 4]);
            pa[4] = __float_as_uint(Ps[(rw + g + 16) * FQS + 8 * s + tig]);
            pa[5] = __float_as_uint(Ps[(rw + g + 24) * FQS + 8 * s + tig]);
            pa[6] = __float_as_uint(Ps[(rw + g + 16) * FQS + 8 * s + tig + 4]);
            pa[7] = __float_as_uint(Ps[(rw + g + 24) * FQS + 8 * s + tig + 4]);
#pragma unroll
            for (int j = 0; j < 8; j++) {
                unsigned b0 = __float_as_uint(Vb[(8 * s + tig) * FVS + 8 * j + g]);
                unsigned b1 = __float_as_uint(Vb[(8 * s + tig + 4) * FVS + 8 * j + g]);
                mma8(&acc[j][0], pa, b0, b1);
                mma8(&acc[j][4], pa + 4, b0, b1);
            }
        }
    }

#pragma unroll
    for (int t = 0; t < 4; t++) {
        lsum[t] += __shfl_xor_sync(0xffffffffu, lsum[t], 1);
        lsum[t] += __shfl_xor_sync(0xffffffffu, lsum[t], 2);
    }
    float inv[4];
#pragma unroll
    for (int t = 0; t < 4; t++) inv[t] = 1.0f / lsum[t];
#pragma unroll
    for (int j = 0; j < 8; j++) {
        int col = h * DK + 8 * j + 2 * tig;
#pragma unroll
        for (int t = 0; t < 4; t++) {
            *(float2*)&CTX[(size_t)(b * SEQ + q0 + rw + g + 8 * t) * DM + col] =
                make_float2(rna_tf32(acc[j][2 * t] * inv[t]),
                            rna_tf32(acc[j][2 * t + 1] * inv[t]));
        }
    }
}

// ---------------- in-place RMSNorm ----------------
__global__ void __launch_bounds__(256) rmsnorm_kernel(float* __restrict__ out,
                                                      const float* __restrict__ gamma) {
    int row = blockIdx.x;
    int tid = threadIdx.x;
    float4 x = *(const float4*)&out[(size_t)row * DM + (tid << 2)];
    float ss = x.x * x.x + x.y * x.y + x.z * x.z + x.w * x.w;
    __shared__ float red[8];
#pragma unroll
    for (int o = 16; o > 0; o >>= 1) ss += __shfl_xor_sync(0xffffffffu, ss, o);
    if ((tid & 31) == 0) red[tid >> 5] = ss;
    __syncthreads();
    if (tid < 8) {
        float sv = red[tid];
#pragma unroll
        for (int o = 4; o > 0; o >>= 1) sv += __shfl_xor_sync(0xffu, sv, o);
        if (tid == 0) red[0] = sv;
    }
    __syncthreads();
    float rms = rsqrtf(red[0] * (1.0f / (float)DM) + 1e-6f);
    float4 g = *(const float4*)&gamma[tid << 2];
    x.x *= rms * g.x; x.y *= rms * g.y; x.z *= rms * g.z; x.w *= rms * g.w;
    *(float4*)&out[(size_t)row * DM + (tid << 2)] = x;
}

// ---------------- launch ----------------
extern "C" void kernel_launch(void* const* d_in, const int* in_sizes, int n_in,
                              void* d_out, int out_size) {
    (void)in_sizes; (void)n_in; (void)out_size;
    const float* Q    = (const float*)d_in[0];
    const float* K    = (const float*)d_in[1];
    const float* V    = (const float*)d_in[2];
    const int*   mask = (const int*)d_in[3];
    const float* wq   = (const float*)d_in[4];
    const float* bq   = (const float*)d_in[5];
    const float* wk   = (const float*)d_in[6];
    const float* bk   = (const float*)d_in[7];
    const float* wv   = (const float*)d_in[8];
    const float* bv   = (const float*)d_in[9];
    const float* wo   = (const float*)d_in[10];
    const float* bo   = (const float*)d_in[11];
    const float* wnq  = (const float*)d_in[12];
    const float* bnq  = (const float*)d_in[13];
    const float* wnk  = (const float*)d_in[14];
    const float* bnk  = (const float*)d_in[15];
    const float* temp = (const float*)d_in[16];
    const float* gamma= (const float*)d_in[17];
    float* out = (float*)d_out;

    float *WQP, *WKP, *WVR, *WOR, *BQP, *BKP, *QR, *KR, *VR, *QFp, *KFp, *VPp, *CTXp;
    unsigned long long* PM;
    cudaGetSymbolAddress((void**)&WQP, g_WQP);
    cudaGetSymbolAddress((void**)&WKP, g_WKP);
    cudaGetSymbolAddress((void**)&WVR, g_WVR);
    cudaGetSymbolAddress((void**)&WOR, g_WOR);
    cudaGetSymbolAddress((void**)&BQP, g_BQP);
    cudaGetSymbolAddress((void**)&BKP, g_BKP);
    cudaGetSymbolAddress((void**)&QR, g_QR);
    cudaGetSymbolAddress((void**)&KR, g_KR);
    cudaGetSymbolAddress((void**)&VR, g_VR);
    cudaGetSymbolAddress((void**)&QFp, g_QF);
    cudaGetSymbolAddress((void**)&KFp, g_KF);
    cudaGetSymbolAddress((void**)&VPp, g_VP);
    cudaGetSymbolAddress((void**)&CTXp, g_CTX);
    cudaGetSymbolAddress((void**)&PM, g_PM);

    cudaFuncSetAttribute(gemm_tc, cudaFuncAttributeMaxDynamicSharedMemorySize, GEMM_SMEM);
    cudaFuncSetAttribute(gemm_qkv, cudaFuncAttributeMaxDynamicSharedMemorySize, GEMM_SMEM);
    cudaFuncSetAttribute(flash_tc, cudaFuncAttributeMaxDynamicSharedMemorySize, FLASH_SMEM);

    // prepasses
    round_copy3<<<dim3(512, 1, 3), 256>>>(Q, QR, K, KR, V, VR, NTOK * DM / 4);
    round_copy3<<<dim3(128, 1, 2), 256>>>(wv, WVR, wo, WOR, wo, WOR, DM * DM / 4);
    pack_mask<<<(SEQ * NKT32 + 255) / 256, 256>>>(mask, PM);
    fold3<<<dim3(DM, 1, 2), 256>>>(wq, bq, wnq, bnq, WQP, BQP,
                                   wk, bk, wnk, bnk, WKP, BKP);

    // QKV projections in one launch
    dim3 ggrid(DM / GBN, NTOK / GBM, 3);
    gemm_qkv<<<ggrid, 256, GEMM_SMEM>>>(QR, WQP, BQP, QFp,
                                        KR, WKP, BKP, KFp,
                                        VR, WVR, bv, VPp);

    dim3 agrid(SEQ / FBM, NH, 2);
    flash_tc<<<agrid, 256, FLASH_SMEM>>>(QFp, KFp, VPp, PM, temp, CTXp);

    dim3 ogrid(DM / GBN, NTOK / GBM);
    gemm_tc<<<ogrid, 256, GEMM_SMEM>>>(CTXp, WOR, bo, out, 0);
    rmsnorm_kernel<<<NTOK, 256>>>(out, gamma);
}